// round 9
// baseline (speedup 1.0000x reference)
#include <cuda_runtime.h>
#include <cuda_fp16.h>
#include <math.h>
#include <stdint.h>

#define BB 2
#define TT 2048
#define CC 1024
#define HH 16
#define DHD 64
#define NTOK (BB*TT)   // 4096

// Scratch (allocation-free: __device__ globals)
__device__ __half g_xh[NTOK*CC];        // x as f16
__device__ __half g_q[BB*HH*TT*DHD];    // f16, [bh][t][d]
__device__ __half g_k[BB*HH*TT*DHD];    // f16, [bh][t][d]
__device__ __half g_vt[BB*HH*DHD*TT];   // f16, TRANSPOSED [bh][d][t]
__device__ __half g_ao[NTOK*CC];        // attention out f16, token-major
__device__ __half g_wqkvT[3*CC*CC];     // W_qkv^T f16, [3072][1024]
__device__ __half g_wprojT[CC*CC];      // W_proj^T f16, [1024][1024]

// ---------------------------------------------------------------------------
__device__ __forceinline__ float ex2(float x) {
    float r; asm("ex2.approx.f32 %0, %1;" : "=f"(r) : "f"(x)); return r;
}
__device__ __forceinline__ uint32_t smem_u32(const void* p) {
    return (uint32_t)__cvta_generic_to_shared(p);
}
__device__ __forceinline__ void ldsm4(uint32_t& r0, uint32_t& r1, uint32_t& r2,
                                      uint32_t& r3, uint32_t a) {
    asm volatile("ldmatrix.sync.aligned.m8n8.x4.shared.b16 {%0,%1,%2,%3},[%4];"
                 : "=r"(r0), "=r"(r1), "=r"(r2), "=r"(r3) : "r"(a));
}
// f16 MMA: D(f32) += A(f16 m16k16) * B(f16 k16n8)
__device__ __forceinline__ void mma16(float4& d, const uint32_t* a,
                                      uint32_t b0, uint32_t b1) {
    asm volatile("mma.sync.aligned.m16n8k16.row.col.f32.f16.f16.f32 "
                 "{%0,%1,%2,%3},{%4,%5,%6,%7},{%8,%9},{%0,%1,%2,%3};"
                 : "+f"(d.x), "+f"(d.y), "+f"(d.z), "+f"(d.w)
                 : "r"(a[0]), "r"(a[1]), "r"(a[2]), "r"(a[3]), "r"(b0), "r"(b1));
}
__device__ __forceinline__ void cp16(uint32_t s, const void* g) {
    asm volatile("cp.async.cg.shared.global [%0], [%1], 16;" :: "r"(s), "l"(g));
}
__device__ __forceinline__ void cp_commit() {
    asm volatile("cp.async.commit_group;");
}
template<int N>
__device__ __forceinline__ void cp_wait() {
    asm volatile("cp.async.wait_group %0;" :: "n"(N));
}

// ---------------------------------------------------------------------------
__global__ void cvt_f32_f16(const float* __restrict__ in, __half* __restrict__ out,
                            int n4)
{
    int i = blockIdx.x * blockDim.x + threadIdx.x;
    if (i < n4) {
        float4 v = ((const float4*)in)[i];
        __half2 h0 = __floats2half2_rn(v.x, v.y);
        __half2 h1 = __floats2half2_rn(v.z, v.w);
        ((uint2*)out)[i] = make_uint2(*(uint32_t*)&h0, *(uint32_t*)&h1);
    }
}

// Transpose + f16-convert: Wt[n*K + k] = f16(W[k*N + n])
__global__ void transpose_cvt_h(const float* __restrict__ W, __half* __restrict__ Wt,
                                int K, int N)
{
    __shared__ float tile[32][33];
    const int n0 = blockIdx.x * 32, k0 = blockIdx.y * 32;
    const int tx = threadIdx.x, ty = threadIdx.y;
    #pragma unroll
    for (int i = ty; i < 32; i += 8)
        tile[i][tx] = W[(size_t)(k0 + i) * N + n0 + tx];
    __syncthreads();
    #pragma unroll
    for (int i = ty; i < 32; i += 8)
        Wt[(size_t)(n0 + i) * K + k0 + tx] = __float2half_rn(tile[tx][i]);
}

// ---------------------------------------------------------------------------
// f16 tensor-core GEMM, 5-stage cp.async ring, 4 warps of 64x64.
// C[M,N] = A[M,K](f16) @ Bt[N,K]^T(f16) + bias
// K-tile = 32 (two k16 sub-steps). Rows padded to 80 B (conflict-free LDSM).
// MODE 0: scatter into g_q/g_k (f16, [bh][t][d]) and g_vt (f16, [bh][d][t])
// MODE 1: fp32 epilogue into Out
// ---------------------------------------------------------------------------
#define GSTAGE 10240   // bytes per matrix per stage: 128 rows x 80 B
#define GS 5           // stages

template<int MODE>
__global__ __launch_bounds__(128, 2)
void mma_gemm(const __half* __restrict__ A, const __half* __restrict__ Bt,
              const float* __restrict__ bias, float* __restrict__ Out,
              int M, int N, int K)
{
    extern __shared__ __align__(16) char dsm[];
    const uint32_t sA = smem_u32(dsm);            // GS stages A
    const uint32_t sB = sA + GS * GSTAGE;         // GS stages B

    const int row0 = blockIdx.y * 128, col0 = blockIdx.x * 128;
    const int tid = threadIdx.x, lane = tid & 31, wid = tid >> 5;
    const int wm = (wid >> 1) * 64, wn = (wid & 1) * 64;
    const int g = lane >> 2, tg = lane & 3;

    float4 c[4][8];
    #pragma unroll
    for (int i = 0; i < 4; i++)
        #pragma unroll
        for (int j = 0; j < 8; j++) c[i][j] = make_float4(0.f, 0.f, 0.f, 0.f);

    // ldmatrix bases: A m16k16 rows = m; B n8k16 rows = n
    const uint32_t aBase = sA + (wm + (lane & 15)) * 80 + (lane >> 4) * 16;
    const uint32_t bBase = sB + (wn + ((lane >> 4) << 3) + (lane & 7)) * 80
                              + ((lane >> 3) & 1) * 16;

    const int NKT = K / 32;   // 32

    auto issueAB = [&](int kt, int buf) {
        #pragma unroll
        for (int c4 = 0; c4 < 4; c4++) {
            cp16(sA + buf * GSTAGE + tid * 80 + c4 * 16,
                 A + (size_t)(row0 + tid) * K + kt * 32 + c4 * 8);
            cp16(sB + buf * GSTAGE + tid * 80 + c4 * 16,
                 Bt + (size_t)(col0 + tid) * K + kt * 32 + c4 * 8);
        }
        cp_commit();
    };

    issueAB(0, 0); issueAB(1, 1); issueAB(2, 2); issueAB(3, 3);

    for (int kt = 0; kt < NKT; kt++) {
        if (kt + 3 < NKT)      cp_wait<3>();
        else if (kt + 2 < NKT) cp_wait<2>();
        else if (kt + 1 < NKT) cp_wait<1>();
        else                   cp_wait<0>();
        __syncthreads();
        if (kt + 4 < NKT) issueAB(kt + 4, (kt + 4) % GS);

        const int buf = kt % GS;
        const uint32_t aB = aBase + buf * GSTAGE;
        const uint32_t bB = bBase + buf * GSTAGE;
        #pragma unroll
        for (int s = 0; s < 2; s++) {
            uint32_t af[4][4], bf[8][2];
            #pragma unroll
            for (int fm = 0; fm < 4; fm++)
                ldsm4(af[fm][0], af[fm][1], af[fm][2], af[fm][3],
                      aB + fm * (16 * 80) + s * 32);
            #pragma unroll
            for (int cb = 0; cb < 4; cb++)
                ldsm4(bf[2*cb][0], bf[2*cb][1], bf[2*cb+1][0], bf[2*cb+1][1],
                      bB + cb * (16 * 80) + s * 32);
            #pragma unroll
            for (int fm = 0; fm < 4; fm++)
                #pragma unroll
                for (int fn = 0; fn < 8; fn++)
                    mma16(c[fm][fn], af[fm], bf[fn][0], bf[fn][1]);
        }
    }

    #pragma unroll
    for (int fm = 0; fm < 4; fm++) {
        #pragma unroll
        for (int fn = 0; fn < 8; fn++) {
            const int m0 = row0 + wm + fm * 16 + g;
            const int m1 = m0 + 8;
            const int n  = col0 + wn + fn * 8 + 2 * tg;
            const float b0v = bias[n], b1v = bias[n + 1];
            float2 lo = make_float2(c[fm][fn].x + b0v, c[fm][fn].y + b1v);
            float2 hi = make_float2(c[fm][fn].z + b0v, c[fm][fn].w + b1v);
            if (MODE == 0) {
                const int which = n >> 10, cc = n & 1023, h = cc >> 6, d = cc & 63;
                const int b = m0 >> 11, t = m0 & 2047;   // same b for m0, m1
                if (which < 2) {
                    __half* dst = (which == 0) ? g_q : g_k;
                    *(__half2*)&dst[((size_t)((b * HH + h) * TT + t)) * DHD + d] =
                        __floats2half2_rn(lo.x, lo.y);
                    *(__half2*)&dst[((size_t)((b * HH + h) * TT + t + 8)) * DHD + d] =
                        __floats2half2_rn(hi.x, hi.y);
                } else {
                    __half* dst = g_vt + (size_t)(b * HH + h) * DHD * TT;
                    dst[(size_t)d * TT + t]           = __float2half_rn(lo.x);
                    dst[(size_t)(d + 1) * TT + t]     = __float2half_rn(lo.y);
                    dst[(size_t)d * TT + t + 8]       = __float2half_rn(hi.x);
                    dst[(size_t)(d + 1) * TT + t + 8] = __float2half_rn(hi.y);
                }
            } else {
                *(float2*)&Out[(size_t)m0 * N + n] = lo;
                *(float2*)&Out[(size_t)m1 * N + n] = hi;
            }
        }
    }
}

// ---------------------------------------------------------------------------
// f16 tensor-core causal flash attention, 4-buffer cp.async KV ring,
// ONE __syncthreads per tile. CTA = (bh, 64-row q tile), 4 warps x m16.
// K-tile = 64 keys. Rows padded to 144 B (72 halves) for conflict-free LDSM.
// ---------------------------------------------------------------------------
#define KVB 9216      // bytes per KV tile: 64 rows x 144 B
#define SCL2E 0.1803368801111204f   // (1/8) * log2(e)

__global__ __launch_bounds__(128)
void attn_kernel()
{
    extern __shared__ __align__(16) char smc[];
    __half* Qs  = (__half*)smc;                 // 64 x 72 (aliased by Ps)
    const uint32_t sQ = smem_u32(smc);
    const uint32_t sK = sQ + KVB;               // 4 x KVB
    const uint32_t sV = sK + 4 * KVB;           // 4 x KVB
    __half* Ps  = Qs;

    const int bh = blockIdx.y;
    const int qt = (int)gridDim.x - 1 - (int)blockIdx.x;  // big tiles first
    const int q0 = qt * 64;
    const int tid = threadIdx.x, lane = tid & 31, wid = tid >> 5;
    const int wm = wid * 16;
    const int g = lane >> 2, tg = lane & 3;

    const __half* Qg = g_q  + (size_t)bh * TT * DHD;
    const __half* Kg = g_k  + (size_t)bh * TT * DHD;
    const __half* Vg = g_vt + (size_t)bh * DHD * TT;

    auto issueKV = [&](int kt, int buf) {
        const int k0 = kt * 64;
        #pragma unroll
        for (int i = 0; i < 4; i++) {
            int idx = tid + i * 128;            // 0..511
            int r = idx >> 3, c8 = (idx & 7) * 8;
            cp16(sK + buf * KVB + r * 144 + c8 * 2,
                 Kg + (size_t)(k0 + r) * DHD + c8);
            cp16(sV + buf * KVB + r * 144 + c8 * 2,
                 Vg + (size_t)r * TT + k0 + c8);
        }
        cp_commit();
    };

    const int NT = qt + 1;

    // prologue: Q + KV0 (group 0), KV1 (group 1), KV2 (group 2)
    // (key rows up to 191 always exist: TT = 2048)
    #pragma unroll
    for (int i = 0; i < 4; i++) {
        int idx = tid + i * 128;
        int r = idx >> 3, c8 = (idx & 7) * 8;
        cp16(sQ + r * 144 + c8 * 2, Qg + (size_t)(q0 + r) * DHD + c8);
        cp16(sK + r * 144 + c8 * 2, Kg + (size_t)r * DHD + c8);
        cp16(sV + r * 144 + c8 * 2, Vg + (size_t)r * TT + c8);
    }
    cp_commit();
    issueKV(1, 1);
    issueKV(2, 2);

    // ldmatrix bases
    const uint32_t aQ = sQ + (wm + (lane & 15)) * 144 + (lane >> 4) * 16;
    const uint32_t kOff = (((lane >> 4) << 3) + (lane & 7)) * 144
                        + ((lane >> 3) & 1) * 16;
    const uint32_t aP = aQ;   // Ps aliases Qs

    uint32_t qf[4][4];
    float4 o[8];
    #pragma unroll
    for (int fn = 0; fn < 8; fn++) o[fn] = make_float4(0.f, 0.f, 0.f, 0.f);
    float m0 = -INFINITY, m1 = -INFINITY, l0 = 0.f, l1 = 0.f;
    const int r0g = q0 + wm + g, r1g = r0g + 8;

    for (int kt = 0; kt < NT; kt++) {
        const int k0 = kt * 64;
        if (kt + 2 < NT)      cp_wait<2>();
        else if (kt + 1 < NT) cp_wait<1>();
        else                  cp_wait<0>();
        __syncthreads();
        // buffer (kt+3)%4 was last read in iteration kt-1; the sync above
        // fences all warps past that compute, so reissue is safe here.
        if (kt + 3 < NT) issueKV(kt + 3, (kt + 3) & 3);

        if (kt == 0) {
            #pragma unroll
            for (int kc = 0; kc < 4; kc++)
                ldsm4(qf[kc][0], qf[kc][1], qf[kc][2], qf[kc][3], aQ + kc * 32);
        }

        const int buf = kt & 3;
        const uint32_t bK = sK + buf * KVB + kOff;
        const uint32_t bV = sV + buf * KVB + kOff;

        // S = Q K^T  (m16 x n64), raw scores
        float4 s[8];
        #pragma unroll
        for (int fn = 0; fn < 8; fn++) s[fn] = make_float4(0.f, 0.f, 0.f, 0.f);
        #pragma unroll
        for (int kc = 0; kc < 4; kc++) {
            #pragma unroll
            for (int cb = 0; cb < 4; cb++) {
                uint32_t b0, b1, b2, b3;
                ldsm4(b0, b1, b2, b3, bK + cb * (16 * 144) + kc * 32);
                mma16(s[2*cb],   qf[kc], b0, b1);
                mma16(s[2*cb+1], qf[kc], b2, b3);
            }
        }

        // causal mask (only the diagonal tile)
        if (kt == qt) {
            #pragma unroll
            for (int fn = 0; fn < 8; fn++) {
                int c0 = k0 + fn * 8 + 2 * tg, c1 = c0 + 1;
                if (c0 > r0g) s[fn].x = -INFINITY;
                if (c1 > r0g) s[fn].y = -INFINITY;
                if (c0 > r1g) s[fn].z = -INFINITY;
                if (c1 > r1g) s[fn].w = -INFINITY;
            }
        }

        // online softmax in base-2 domain (rows g, g+8)
        float rmax0 = -INFINITY, rmax1 = -INFINITY;
        #pragma unroll
        for (int fn = 0; fn < 8; fn++) {
            rmax0 = fmaxf(rmax0, fmaxf(s[fn].x, s[fn].y));
            rmax1 = fmaxf(rmax1, fmaxf(s[fn].z, s[fn].w));
        }
        rmax0 = fmaxf(rmax0, __shfl_xor_sync(0xffffffffu, rmax0, 1));
        rmax0 = fmaxf(rmax0, __shfl_xor_sync(0xffffffffu, rmax0, 2));
        rmax1 = fmaxf(rmax1, __shfl_xor_sync(0xffffffffu, rmax1, 1));
        rmax1 = fmaxf(rmax1, __shfl_xor_sync(0xffffffffu, rmax1, 2));
        const float mn0 = fmaxf(m0, rmax0), mn1 = fmaxf(m1, rmax1);
        const float al0 = ex2((m0 - mn0) * SCL2E), al1 = ex2((m1 - mn1) * SCL2E);
        m0 = mn0; m1 = mn1;
        float rs0 = 0.f, rs1 = 0.f;
        #pragma unroll
        for (int fn = 0; fn < 8; fn++) {
            s[fn].x = ex2((s[fn].x - mn0) * SCL2E);
            s[fn].y = ex2((s[fn].y - mn0) * SCL2E);
            s[fn].z = ex2((s[fn].z - mn1) * SCL2E);
            s[fn].w = ex2((s[fn].w - mn1) * SCL2E);
            rs0 += s[fn].x + s[fn].y;
            rs1 += s[fn].z + s[fn].w;
        }
        rs0 += __shfl_xor_sync(0xffffffffu, rs0, 1);
        rs0 += __shfl_xor_sync(0xffffffffu, rs0, 2);
        rs1 += __shfl_xor_sync(0xffffffffu, rs1, 1);
        rs1 += __shfl_xor_sync(0xffffffffu, rs1, 2);
        l0 = l0 * al0 + rs0;
        l1 = l1 * al1 + rs1;
        #pragma unroll
        for (int fn = 0; fn < 8; fn++) {
            o[fn].x *= al0; o[fn].y *= al0;
            o[fn].z *= al1; o[fn].w *= al1;
        }

        // P -> warp-private smem rows (f16)
        #pragma unroll
        for (int fn = 0; fn < 8; fn++) {
            *(__half2*)&Ps[(wm + g) * 72 + fn * 8 + 2 * tg] =
                __floats2half2_rn(s[fn].x, s[fn].y);
            *(__half2*)&Ps[(wm + g + 8) * 72 + fn * 8 + 2 * tg] =
                __floats2half2_rn(s[fn].z, s[fn].w);
        }
        __syncwarp();

        // O += P @ V  (B operand from transposed V: rows = d, cols = key)
        #pragma unroll
        for (int kc = 0; kc < 4; kc++) {
            uint32_t pf[4];
            ldsm4(pf[0], pf[1], pf[2], pf[3], aP + kc * 32);
            #pragma unroll
            for (int cb = 0; cb < 4; cb++) {
                uint32_t b0, b1, b2, b3;
                ldsm4(b0, b1, b2, b3, bV + cb * (16 * 144) + kc * 32);
                mma16(o[2*cb],   pf, b0, b1);
                mma16(o[2*cb+1], pf, b2, b3);
            }
        }
    }

    // finalize -> g_ao (f16), token-major
    const int b = bh >> 4, h = bh & 15;
    const float inv0 = 1.f / l0, inv1 = 1.f / l1;
    #pragma unroll
    for (int fn = 0; fn < 8; fn++) {
        const int d = fn * 8 + 2 * tg;
        *(__half2*)&g_ao[(size_t)(b * TT + r0g) * CC + h * 64 + d] =
            __floats2half2_rn(o[fn].x * inv0, o[fn].y * inv0);
        *(__half2*)&g_ao[(size_t)(b * TT + r1g) * CC + h * 64 + d] =
            __floats2half2_rn(o[fn].z * inv1, o[fn].w * inv1);
    }
}

// ---------------------------------------------------------------------------
extern "C" void kernel_launch(void* const* d_in, const int* in_sizes, int n_in,
                              void* d_out, int out_size)
{
    const float* x      = (const float*)d_in[0];
    const float* W_qkv  = (const float*)d_in[1];
    const float* b_qkv  = (const float*)d_in[2];
    const float* W_proj = (const float*)d_in[3];
    const float* b_proj = (const float*)d_in[4];
    float* out = (float*)d_out;

    __half* xh;     cudaGetSymbolAddress((void**)&xh,     g_xh);
    __half* wqkvT;  cudaGetSymbolAddress((void**)&wqkvT,  g_wqkvT);
    __half* wprojT; cudaGetSymbolAddress((void**)&wprojT, g_wprojT);
    __half* ao;     cudaGetSymbolAddress((void**)&ao,     g_ao);

    // 0) convert x to f16; transpose+convert weights to f16
    cvt_f32_f16<<<(NTOK*CC/4 + 255)/256, 256>>>(x, xh, NTOK*CC/4);
    transpose_cvt_h<<<dim3(3*CC/32, CC/32), dim3(32, 8)>>>(W_qkv,  wqkvT,  CC, 3*CC);
    transpose_cvt_h<<<dim3(CC/32,   CC/32), dim3(32, 8)>>>(W_proj, wprojT, CC, CC);

    const int gemm_smem = 2 * GS * GSTAGE;   // 102400
    cudaFuncSetAttribute(mma_gemm<0>, cudaFuncAttributeMaxDynamicSharedMemorySize,
                         gemm_smem);
    cudaFuncSetAttribute(mma_gemm<1>, cudaFuncAttributeMaxDynamicSharedMemorySize,
                         gemm_smem);

    // 1) QKV GEMM (f16 mma) + scatter
    mma_gemm<0><<<dim3(3*CC/128, NTOK/128), 128, gemm_smem>>>(xh, wqkvT, b_qkv,
                                                              nullptr, NTOK, 3*CC, CC);

    // 2) causal flash attention (f16 mma, 81 KB smem/CTA, 2 CTAs/SM)
    const int attn_smem = 9 * KVB;      // 82944
    cudaFuncSetAttribute(attn_kernel, cudaFuncAttributeMaxDynamicSharedMemorySize,
                         attn_smem);
    attn_kernel<<<dim3(TT/64, BB*HH), 128, attn_smem>>>();

    // 3) output projection (f16 mma)
    mma_gemm<1><<<dim3(CC/128, NTOK/128), 128, gemm_smem>>>(ao, wprojT, b_proj,
                                                            out, NTOK, CC, CC);
}

// round 10
// speedup vs baseline: 1.1927x; 1.1927x over previous
#include <cuda_runtime.h>
#include <cuda_fp16.h>
#include <math.h>
#include <stdint.h>

#define BB 2
#define TT 2048
#define CC 1024
#define HH 16
#define DHD 64
#define NTOK (BB*TT)   // 4096

// Scratch (allocation-free: __device__ globals)
__device__ __half g_xh[NTOK*CC];        // x as f16
__device__ __half g_q[BB*HH*TT*DHD];    // f16, [bh][t][d]
__device__ __half g_k[BB*HH*TT*DHD];    // f16, [bh][t][d]
__device__ __half g_vt[BB*HH*DHD*TT];   // f16, TRANSPOSED [bh][d][t]
__device__ __half g_ao[NTOK*CC];        // attention out f16, token-major
__device__ __half g_wqkvT[3*CC*CC];     // W_qkv^T f16, [3072][1024]
__device__ __half g_wprojT[CC*CC];      // W_proj^T f16, [1024][1024]

// ---------------------------------------------------------------------------
__device__ __forceinline__ float ex2(float x) {
    float r; asm("ex2.approx.f32 %0, %1;" : "=f"(r) : "f"(x)); return r;
}
__device__ __forceinline__ uint32_t smem_u32(const void* p) {
    return (uint32_t)__cvta_generic_to_shared(p);
}
__device__ __forceinline__ void ldsm4(uint32_t& r0, uint32_t& r1, uint32_t& r2,
                                      uint32_t& r3, uint32_t a) {
    asm volatile("ldmatrix.sync.aligned.m8n8.x4.shared.b16 {%0,%1,%2,%3},[%4];"
                 : "=r"(r0), "=r"(r1), "=r"(r2), "=r"(r3) : "r"(a));
}
// f16 MMA: D(f32) += A(f16 m16k16) * B(f16 k16n8)
__device__ __forceinline__ void mma16(float4& d, const uint32_t* a,
                                      uint32_t b0, uint32_t b1) {
    asm volatile("mma.sync.aligned.m16n8k16.row.col.f32.f16.f16.f32 "
                 "{%0,%1,%2,%3},{%4,%5,%6,%7},{%8,%9},{%0,%1,%2,%3};"
                 : "+f"(d.x), "+f"(d.y), "+f"(d.z), "+f"(d.w)
                 : "r"(a[0]), "r"(a[1]), "r"(a[2]), "r"(a[3]), "r"(b0), "r"(b1));
}
__device__ __forceinline__ void cp16(uint32_t s, const void* g) {
    asm volatile("cp.async.cg.shared.global [%0], [%1], 16;" :: "r"(s), "l"(g));
}
__device__ __forceinline__ void cp_commit() {
    asm volatile("cp.async.commit_group;");
}
template<int N>
__device__ __forceinline__ void cp_wait() {
    asm volatile("cp.async.wait_group %0;" :: "n"(N));
}

// ---------------------------------------------------------------------------
__global__ void cvt_f32_f16(const float* __restrict__ in, __half* __restrict__ out,
                            int n4)
{
    int i = blockIdx.x * blockDim.x + threadIdx.x;
    if (i < n4) {
        float4 v = ((const float4*)in)[i];
        __half2 h0 = __floats2half2_rn(v.x, v.y);
        __half2 h1 = __floats2half2_rn(v.z, v.w);
        ((uint2*)out)[i] = make_uint2(*(uint32_t*)&h0, *(uint32_t*)&h1);
    }
}

// Transpose + f16-convert: Wt[n*K + k] = f16(W[k*N + n])
__global__ void transpose_cvt_h(const float* __restrict__ W, __half* __restrict__ Wt,
                                int K, int N)
{
    __shared__ float tile[32][33];
    const int n0 = blockIdx.x * 32, k0 = blockIdx.y * 32;
    const int tx = threadIdx.x, ty = threadIdx.y;
    #pragma unroll
    for (int i = ty; i < 32; i += 8)
        tile[i][tx] = W[(size_t)(k0 + i) * N + n0 + tx];
    __syncthreads();
    #pragma unroll
    for (int i = ty; i < 32; i += 8)
        Wt[(size_t)(n0 + i) * K + k0 + tx] = __float2half_rn(tile[tx][i]);
}

// ---------------------------------------------------------------------------
// f16 tensor-core GEMM, 256x128 CTA tile, 256 threads (8 warps of 64x64),
// 3-stage cp.async ring. C[M,N] = A[M,K](f16) @ Bt[N,K]^T(f16) + bias
// K-tile = 32 (two k16 sub-steps). Rows padded to 80 B (conflict-free LDSM).
// MODE 0: scatter into g_q/g_k (f16, [bh][t][d]) and g_vt (f16, [bh][d][t])
// MODE 1: fp32 epilogue into Out
// ---------------------------------------------------------------------------
#define ASTG 20480     // A stage: 256 rows x 80 B
#define BSTG 10240     // B stage: 128 rows x 80 B

template<int MODE>
__global__ __launch_bounds__(256, 1)
void mma_gemm(const __half* __restrict__ A, const __half* __restrict__ Bt,
              const float* __restrict__ bias, float* __restrict__ Out,
              int M, int N, int K)
{
    extern __shared__ __align__(16) char dsm[];
    const uint32_t sA = smem_u32(dsm);            // 3 stages A
    const uint32_t sB = sA + 3 * ASTG;            // 3 stages B

    const int row0 = blockIdx.y * 256, col0 = blockIdx.x * 128;
    const int tid = threadIdx.x, lane = tid & 31, wid = tid >> 5;
    const int wm = (wid >> 1) * 64, wn = (wid & 1) * 64;
    const int g = lane >> 2, tg = lane & 3;

    float4 c[4][8];
    #pragma unroll
    for (int i = 0; i < 4; i++)
        #pragma unroll
        for (int j = 0; j < 8; j++) c[i][j] = make_float4(0.f, 0.f, 0.f, 0.f);

    // ldmatrix bases: A m16k16 rows = m; B n8k16 rows = n
    const uint32_t aBase = sA + (wm + (lane & 15)) * 80 + (lane >> 4) * 16;
    const uint32_t bBase = sB + (wn + ((lane >> 4) << 3) + (lane & 7)) * 80
                              + ((lane >> 3) & 1) * 16;

    const int NKT = K / 32;   // 32

    auto issueAB = [&](int kt, int buf) {
        // A: 256 rows x 4 chunks = 1024 cp16 over 256 threads
        #pragma unroll
        for (int i = 0; i < 4; i++) {
            int idx = tid + i * 256;
            int r = idx >> 2, c4 = idx & 3;
            cp16(sA + buf * ASTG + r * 80 + c4 * 16,
                 A + (size_t)(row0 + r) * K + kt * 32 + c4 * 8);
        }
        // B: 128 rows x 4 chunks = 512 cp16 over 256 threads
        #pragma unroll
        for (int i = 0; i < 2; i++) {
            int idx = tid + i * 256;
            int r = idx >> 2, c4 = idx & 3;
            cp16(sB + buf * BSTG + r * 80 + c4 * 16,
                 Bt + (size_t)(col0 + r) * K + kt * 32 + c4 * 8);
        }
        cp_commit();
    };

    issueAB(0, 0); issueAB(1, 1);

    for (int kt = 0; kt < NKT; kt++) {
        if (kt + 1 < NKT) cp_wait<1>();
        else              cp_wait<0>();
        __syncthreads();
        if (kt + 2 < NKT) issueAB(kt + 2, (kt + 2) % 3);

        const int buf = kt % 3;
        const uint32_t aB = aBase + buf * ASTG;
        const uint32_t bB = bBase + buf * BSTG;
        #pragma unroll
        for (int s = 0; s < 2; s++) {
            uint32_t af[4][4], bf[8][2];
            #pragma unroll
            for (int fm = 0; fm < 4; fm++)
                ldsm4(af[fm][0], af[fm][1], af[fm][2], af[fm][3],
                      aB + fm * (16 * 80) + s * 32);
            #pragma unroll
            for (int cb = 0; cb < 4; cb++)
                ldsm4(bf[2*cb][0], bf[2*cb][1], bf[2*cb+1][0], bf[2*cb+1][1],
                      bB + cb * (16 * 80) + s * 32);
            #pragma unroll
            for (int fm = 0; fm < 4; fm++)
                #pragma unroll
                for (int fn = 0; fn < 8; fn++)
                    mma16(c[fm][fn], af[fm], bf[fn][0], bf[fn][1]);
        }
    }

    #pragma unroll
    for (int fm = 0; fm < 4; fm++) {
        #pragma unroll
        for (int fn = 0; fn < 8; fn++) {
            const int m0 = row0 + wm + fm * 16 + g;
            const int m1 = m0 + 8;
            const int n  = col0 + wn + fn * 8 + 2 * tg;
            const float b0v = bias[n], b1v = bias[n + 1];
            float2 lo = make_float2(c[fm][fn].x + b0v, c[fm][fn].y + b1v);
            float2 hi = make_float2(c[fm][fn].z + b0v, c[fm][fn].w + b1v);
            if (MODE == 0) {
                const int which = n >> 10, cc = n & 1023, h = cc >> 6, d = cc & 63;
                const int b = m0 >> 11, t = m0 & 2047;   // same b for m0, m1
                if (which < 2) {
                    __half* dst = (which == 0) ? g_q : g_k;
                    *(__half2*)&dst[((size_t)((b * HH + h) * TT + t)) * DHD + d] =
                        __floats2half2_rn(lo.x, lo.y);
                    *(__half2*)&dst[((size_t)((b * HH + h) * TT + t + 8)) * DHD + d] =
                        __floats2half2_rn(hi.x, hi.y);
                } else {
                    __half* dst = g_vt + (size_t)(b * HH + h) * DHD * TT;
                    dst[(size_t)d * TT + t]           = __float2half_rn(lo.x);
                    dst[(size_t)(d + 1) * TT + t]     = __float2half_rn(lo.y);
                    dst[(size_t)d * TT + t + 8]       = __float2half_rn(hi.x);
                    dst[(size_t)(d + 1) * TT + t + 8] = __float2half_rn(hi.y);
                }
            } else {
                *(float2*)&Out[(size_t)m0 * N + n] = lo;
                *(float2*)&Out[(size_t)m1 * N + n] = hi;
            }
        }
    }
}

// ---------------------------------------------------------------------------
// f16 tensor-core causal flash attention, 2-stage cp.async KV ring (R8 version).
// CTA = (bh, 64-row q tile), 4 warps x m16. K-tile = 64 keys.
// Rows padded to 144 B (72 halves) for conflict-free LDSM.
// ---------------------------------------------------------------------------
#define KVB 9216      // bytes per KV tile: 64 rows x 144 B
#define SCL2E 0.1803368801111204f   // (1/8) * log2(e)

__global__ __launch_bounds__(128)
void attn_kernel()
{
    extern __shared__ __align__(16) char smc[];
    __half* Qs  = (__half*)smc;                 // 64 x 72 (aliased by Ps)
    const uint32_t sQ = smem_u32(smc);
    const uint32_t sK = sQ + KVB;               // 2 x KVB
    const uint32_t sV = sK + 2 * KVB;           // 2 x KVB
    __half* Ps  = Qs;

    const int bh = blockIdx.y;
    const int qt = (int)gridDim.x - 1 - (int)blockIdx.x;  // big tiles first
    const int q0 = qt * 64;
    const int tid = threadIdx.x, lane = tid & 31, wid = tid >> 5;
    const int wm = wid * 16;
    const int g = lane >> 2, tg = lane & 3;

    const __half* Qg = g_q  + (size_t)bh * TT * DHD;
    const __half* Kg = g_k  + (size_t)bh * TT * DHD;
    const __half* Vg = g_vt + (size_t)bh * DHD * TT;

    auto issueKV = [&](int kt, int buf) {
        const int k0 = kt * 64;
        #pragma unroll
        for (int i = 0; i < 4; i++) {
            int idx = tid + i * 128;            // 0..511
            int r = idx >> 3, c8 = (idx & 7) * 8;
            cp16(sK + buf * KVB + r * 144 + c8 * 2,
                 Kg + (size_t)(k0 + r) * DHD + c8);
            cp16(sV + buf * KVB + r * 144 + c8 * 2,
                 Vg + (size_t)r * TT + k0 + c8);
        }
        cp_commit();
    };

    const int NT = qt + 1;

    // prologue: Q + KV0 (group 0), KV1 (group 1)
    #pragma unroll
    for (int i = 0; i < 4; i++) {
        int idx = tid + i * 128;
        int r = idx >> 3, c8 = (idx & 7) * 8;
        cp16(sQ + r * 144 + c8 * 2, Qg + (size_t)(q0 + r) * DHD + c8);
        cp16(sK + r * 144 + c8 * 2, Kg + (size_t)r * DHD + c8);
        cp16(sV + r * 144 + c8 * 2, Vg + (size_t)r * TT + c8);
    }
    cp_commit();
    issueKV(1, 1);   // keys 64..127 always exist (TT=2048)

    // ldmatrix bases
    const uint32_t aQ = sQ + (wm + (lane & 15)) * 144 + (lane >> 4) * 16;
    const uint32_t kOff = (((lane >> 4) << 3) + (lane & 7)) * 144
                        + ((lane >> 3) & 1) * 16;
    const uint32_t aP = aQ;   // Ps aliases Qs

    uint32_t qf[4][4];
    float4 o[8];
    #pragma unroll
    for (int fn = 0; fn < 8; fn++) o[fn] = make_float4(0.f, 0.f, 0.f, 0.f);
    float m0 = -INFINITY, m1 = -INFINITY, l0 = 0.f, l1 = 0.f;
    const int r0g = q0 + wm + g, r1g = r0g + 8;

    for (int kt = 0; kt < NT; kt++) {
        const int k0 = kt * 64;
        if (kt + 1 < NT) cp_wait<1>();
        else             cp_wait<0>();
        __syncthreads();

        if (kt == 0) {
            #pragma unroll
            for (int kc = 0; kc < 4; kc++)
                ldsm4(qf[kc][0], qf[kc][1], qf[kc][2], qf[kc][3], aQ + kc * 32);
        }

        const int buf = kt & 1;
        const uint32_t bK = sK + buf * KVB + kOff;
        const uint32_t bV = sV + buf * KVB + kOff;

        // S = Q K^T  (m16 x n64), raw scores
        float4 s[8];
        #pragma unroll
        for (int fn = 0; fn < 8; fn++) s[fn] = make_float4(0.f, 0.f, 0.f, 0.f);
        #pragma unroll
        for (int kc = 0; kc < 4; kc++) {
            #pragma unroll
            for (int cb = 0; cb < 4; cb++) {
                uint32_t b0, b1, b2, b3;
                ldsm4(b0, b1, b2, b3, bK + cb * (16 * 144) + kc * 32);
                mma16(s[2*cb],   qf[kc], b0, b1);
                mma16(s[2*cb+1], qf[kc], b2, b3);
            }
        }

        // causal mask (only the diagonal tile)
        if (kt == qt) {
            #pragma unroll
            for (int fn = 0; fn < 8; fn++) {
                int c0 = k0 + fn * 8 + 2 * tg, c1 = c0 + 1;
                if (c0 > r0g) s[fn].x = -INFINITY;
                if (c1 > r0g) s[fn].y = -INFINITY;
                if (c0 > r1g) s[fn].z = -INFINITY;
                if (c1 > r1g) s[fn].w = -INFINITY;
            }
        }

        // online softmax in base-2 domain (rows g, g+8)
        float rmax0 = -INFINITY, rmax1 = -INFINITY;
        #pragma unroll
        for (int fn = 0; fn < 8; fn++) {
            rmax0 = fmaxf(rmax0, fmaxf(s[fn].x, s[fn].y));
            rmax1 = fmaxf(rmax1, fmaxf(s[fn].z, s[fn].w));
        }
        rmax0 = fmaxf(rmax0, __shfl_xor_sync(0xffffffffu, rmax0, 1));
        rmax0 = fmaxf(rmax0, __shfl_xor_sync(0xffffffffu, rmax0, 2));
        rmax1 = fmaxf(rmax1, __shfl_xor_sync(0xffffffffu, rmax1, 1));
        rmax1 = fmaxf(rmax1, __shfl_xor_sync(0xffffffffu, rmax1, 2));
        const float mn0 = fmaxf(m0, rmax0), mn1 = fmaxf(m1, rmax1);
        const float al0 = ex2((m0 - mn0) * SCL2E), al1 = ex2((m1 - mn1) * SCL2E);
        m0 = mn0; m1 = mn1;
        float rs0 = 0.f, rs1 = 0.f;
        #pragma unroll
        for (int fn = 0; fn < 8; fn++) {
            s[fn].x = ex2((s[fn].x - mn0) * SCL2E);
            s[fn].y = ex2((s[fn].y - mn0) * SCL2E);
            s[fn].z = ex2((s[fn].z - mn1) * SCL2E);
            s[fn].w = ex2((s[fn].w - mn1) * SCL2E);
            rs0 += s[fn].x + s[fn].y;
            rs1 += s[fn].z + s[fn].w;
        }
        rs0 += __shfl_xor_sync(0xffffffffu, rs0, 1);
        rs0 += __shfl_xor_sync(0xffffffffu, rs0, 2);
        rs1 += __shfl_xor_sync(0xffffffffu, rs1, 1);
        rs1 += __shfl_xor_sync(0xffffffffu, rs1, 2);
        l0 = l0 * al0 + rs0;
        l1 = l1 * al1 + rs1;
        #pragma unroll
        for (int fn = 0; fn < 8; fn++) {
            o[fn].x *= al0; o[fn].y *= al0;
            o[fn].z *= al1; o[fn].w *= al1;
        }

        // P -> warp-private smem rows (f16)
        #pragma unroll
        for (int fn = 0; fn < 8; fn++) {
            *(__half2*)&Ps[(wm + g) * 72 + fn * 8 + 2 * tg] =
                __floats2half2_rn(s[fn].x, s[fn].y);
            *(__half2*)&Ps[(wm + g + 8) * 72 + fn * 8 + 2 * tg] =
                __floats2half2_rn(s[fn].z, s[fn].w);
        }
        __syncwarp();

        // O += P @ V  (B operand from transposed V: rows = d, cols = key)
        #pragma unroll
        for (int kc = 0; kc < 4; kc++) {
            uint32_t pf[4];
            ldsm4(pf[0], pf[1], pf[2], pf[3], aP + kc * 32);
            #pragma unroll
            for (int cb = 0; cb < 4; cb++) {
                uint32_t b0, b1, b2, b3;
                ldsm4(b0, b1, b2, b3, bV + cb * (16 * 144) + kc * 32);
                mma16(o[2*cb],   pf, b0, b1);
                mma16(o[2*cb+1], pf, b2, b3);
            }
        }

        // free this buffer for kt+2, then prefetch
        __syncthreads();
        if (kt + 2 < NT) issueKV(kt + 2, buf);
    }

    // finalize -> g_ao (f16), token-major
    const int b = bh >> 4, h = bh & 15;
    const float inv0 = 1.f / l0, inv1 = 1.f / l1;
    #pragma unroll
    for (int fn = 0; fn < 8; fn++) {
        const int d = fn * 8 + 2 * tg;
        *(__half2*)&g_ao[(size_t)(b * TT + r0g) * CC + h * 64 + d] =
            __floats2half2_rn(o[fn].x * inv0, o[fn].y * inv0);
        *(__half2*)&g_ao[(size_t)(b * TT + r1g) * CC + h * 64 + d] =
            __floats2half2_rn(o[fn].z * inv1, o[fn].w * inv1);
    }
}

// ---------------------------------------------------------------------------
extern "C" void kernel_launch(void* const* d_in, const int* in_sizes, int n_in,
                              void* d_out, int out_size)
{
    const float* x      = (const float*)d_in[0];
    const float* W_qkv  = (const float*)d_in[1];
    const float* b_qkv  = (const float*)d_in[2];
    const float* W_proj = (const float*)d_in[3];
    const float* b_proj = (const float*)d_in[4];
    float* out = (float*)d_out;

    __half* xh;     cudaGetSymbolAddress((void**)&xh,     g_xh);
    __half* wqkvT;  cudaGetSymbolAddress((void**)&wqkvT,  g_wqkvT);
    __half* wprojT; cudaGetSymbolAddress((void**)&wprojT, g_wprojT);
    __half* ao;     cudaGetSymbolAddress((void**)&ao,     g_ao);

    // 0) convert x to f16; transpose+convert weights to f16
    cvt_f32_f16<<<(NTOK*CC/4 + 255)/256, 256>>>(x, xh, NTOK*CC/4);
    transpose_cvt_h<<<dim3(3*CC/32, CC/32), dim3(32, 8)>>>(W_qkv,  wqkvT,  CC, 3*CC);
    transpose_cvt_h<<<dim3(CC/32,   CC/32), dim3(32, 8)>>>(W_proj, wprojT, CC, CC);

    const int gemm_smem = 3 * (ASTG + BSTG);   // 92160
    cudaFuncSetAttribute(mma_gemm<0>, cudaFuncAttributeMaxDynamicSharedMemorySize,
                         gemm_smem);
    cudaFuncSetAttribute(mma_gemm<1>, cudaFuncAttributeMaxDynamicSharedMemorySize,
                         gemm_smem);

    // 1) QKV GEMM (f16 mma, 256x128 tiles) + scatter
    mma_gemm<0><<<dim3(3*CC/128, NTOK/256), 256, gemm_smem>>>(xh, wqkvT, b_qkv,
                                                              nullptr, NTOK, 3*CC, CC);

    // 2) causal flash attention (f16 mma, 46 KB smem/CTA)
    const int attn_smem = 5 * KVB;      // 46080
    cudaFuncSetAttribute(attn_kernel, cudaFuncAttributeMaxDynamicSharedMemorySize,
                         attn_smem);
    attn_kernel<<<dim3(TT/64, BB*HH), 128, attn_smem>>>();

    // 3) output projection (f16 mma, 256x128 tiles)
    mma_gemm<1><<<dim3(CC/128, NTOK/256), 256, gemm_smem>>>(ao, wprojT, b_proj,
                                                            out, NTOK, CC, CC);
}

// round 11
// speedup vs baseline: 1.2512x; 1.0490x over previous
#include <cuda_runtime.h>
#include <cuda_fp16.h>
#include <math.h>
#include <stdint.h>

#define BB 2
#define TT 2048
#define CC 1024
#define HH 16
#define DHD 64
#define NTOK (BB*TT)   // 4096

// Scratch (allocation-free: __device__ globals)
__device__ __half g_xh[NTOK*CC];        // x as f16
__device__ __half g_q[BB*HH*TT*DHD];    // f16, [bh][t][d]
__device__ __half g_k[BB*HH*TT*DHD];    // f16, [bh][t][d]
__device__ __half g_vt[BB*HH*DHD*TT];   // f16, TRANSPOSED [bh][d][t]
__device__ __half g_ao[NTOK*CC];        // attention out f16, token-major
__device__ __half g_wqkvT[3*CC*CC];     // W_qkv^T f16, [3072][1024]
__device__ __half g_wprojT[CC*CC];      // W_proj^T f16, [1024][1024]

// ---------------------------------------------------------------------------
__device__ __forceinline__ float ex2(float x) {
    float r; asm("ex2.approx.f32 %0, %1;" : "=f"(r) : "f"(x)); return r;
}
__device__ __forceinline__ uint32_t smem_u32(const void* p) {
    return (uint32_t)__cvta_generic_to_shared(p);
}
__device__ __forceinline__ void ldsm4(uint32_t& r0, uint32_t& r1, uint32_t& r2,
                                      uint32_t& r3, uint32_t a) {
    asm volatile("ldmatrix.sync.aligned.m8n8.x4.shared.b16 {%0,%1,%2,%3},[%4];"
                 : "=r"(r0), "=r"(r1), "=r"(r2), "=r"(r3) : "r"(a));
}
// f16 MMA: D(f32) += A(f16 m16k16) * B(f16 k16n8)
__device__ __forceinline__ void mma16(float4& d, const uint32_t* a,
                                      uint32_t b0, uint32_t b1) {
    asm volatile("mma.sync.aligned.m16n8k16.row.col.f32.f16.f16.f32 "
                 "{%0,%1,%2,%3},{%4,%5,%6,%7},{%8,%9},{%0,%1,%2,%3};"
                 : "+f"(d.x), "+f"(d.y), "+f"(d.z), "+f"(d.w)
                 : "r"(a[0]), "r"(a[1]), "r"(a[2]), "r"(a[3]), "r"(b0), "r"(b1));
}
__device__ __forceinline__ void cp16(uint32_t s, const void* g) {
    asm volatile("cp.async.cg.shared.global [%0], [%1], 16;" :: "r"(s), "l"(g));
}
__device__ __forceinline__ void cp_commit() {
    asm volatile("cp.async.commit_group;");
}
template<int N>
__device__ __forceinline__ void cp_wait() {
    asm volatile("cp.async.wait_group %0;" :: "n"(N));
}

// ---------------------------------------------------------------------------
__global__ void cvt_f32_f16(const float* __restrict__ in, __half* __restrict__ out,
                            int n4)
{
    int i = blockIdx.x * blockDim.x + threadIdx.x;
    if (i < n4) {
        float4 v = ((const float4*)in)[i];
        __half2 h0 = __floats2half2_rn(v.x, v.y);
        __half2 h1 = __floats2half2_rn(v.z, v.w);
        ((uint2*)out)[i] = make_uint2(*(uint32_t*)&h0, *(uint32_t*)&h1);
    }
}

// Transpose + f16-convert: Wt[n*K + k] = f16(W[k*N + n])
__global__ void transpose_cvt_h(const float* __restrict__ W, __half* __restrict__ Wt,
                                int K, int N)
{
    __shared__ float tile[32][33];
    const int n0 = blockIdx.x * 32, k0 = blockIdx.y * 32;
    const int tx = threadIdx.x, ty = threadIdx.y;
    #pragma unroll
    for (int i = ty; i < 32; i += 8)
        tile[i][tx] = W[(size_t)(k0 + i) * N + n0 + tx];
    __syncthreads();
    #pragma unroll
    for (int i = ty; i < 32; i += 8)
        Wt[(size_t)(n0 + i) * K + k0 + tx] = __float2half_rn(tile[tx][i]);
}

// ---------------------------------------------------------------------------
// f16 tensor-core GEMM, 256x128 CTA tile, 256 threads (8 warps of 64x64),
// K-tile = 64 (four k16 sub-steps), 3-stage cp.async ring.
// Rows padded to 144 B (conflict-free LDSM: 144/4=36 = 4 mod 32).
// MODE 0: scatter into g_q/g_k (f16, [bh][t][d]) and g_vt (f16, [bh][d][t])
// MODE 1: fp32 epilogue into Out
// ---------------------------------------------------------------------------
#define ASTG 36864     // A stage: 256 rows x 144 B
#define BSTG 18432     // B stage: 128 rows x 144 B

template<int MODE>
__global__ __launch_bounds__(256, 1)
void mma_gemm(const __half* __restrict__ A, const __half* __restrict__ Bt,
              const float* __restrict__ bias, float* __restrict__ Out,
              int M, int N, int K)
{
    extern __shared__ __align__(16) char dsm[];
    const uint32_t sA = smem_u32(dsm);            // 3 stages A
    const uint32_t sB = sA + 3 * ASTG;            // 3 stages B

    const int row0 = blockIdx.y * 256, col0 = blockIdx.x * 128;
    const int tid = threadIdx.x, lane = tid & 31, wid = tid >> 5;
    const int wm = (wid >> 1) * 64, wn = (wid & 1) * 64;
    const int g = lane >> 2, tg = lane & 3;

    float4 c[4][8];
    #pragma unroll
    for (int i = 0; i < 4; i++)
        #pragma unroll
        for (int j = 0; j < 8; j++) c[i][j] = make_float4(0.f, 0.f, 0.f, 0.f);

    // ldmatrix bases: A m16k16 rows = m; B n8k16 rows = n
    const uint32_t aBase = sA + (wm + (lane & 15)) * 144 + (lane >> 4) * 16;
    const uint32_t bBase = sB + (wn + ((lane >> 4) << 3) + (lane & 7)) * 144
                              + ((lane >> 3) & 1) * 16;

    const int NKT = K / 64;   // 16

    auto issueAB = [&](int kt, int buf) {
        // A: 256 rows x 8 chunks = 2048 cp16 over 256 threads
        #pragma unroll
        for (int i = 0; i < 8; i++) {
            int idx = tid + i * 256;
            int r = idx >> 3, c8 = idx & 7;
            cp16(sA + buf * ASTG + r * 144 + c8 * 16,
                 A + (size_t)(row0 + r) * K + kt * 64 + c8 * 8);
        }
        // B: 128 rows x 8 chunks = 1024 cp16 over 256 threads
        #pragma unroll
        for (int i = 0; i < 4; i++) {
            int idx = tid + i * 256;
            int r = idx >> 3, c8 = idx & 7;
            cp16(sB + buf * BSTG + r * 144 + c8 * 16,
                 Bt + (size_t)(col0 + r) * K + kt * 64 + c8 * 8);
        }
        cp_commit();
    };

    issueAB(0, 0); issueAB(1, 1);

    for (int kt = 0; kt < NKT; kt++) {
        if (kt + 1 < NKT) cp_wait<1>();
        else              cp_wait<0>();
        __syncthreads();
        if (kt + 2 < NKT) issueAB(kt + 2, (kt + 2) % 3);

        const int buf = kt % 3;
        const uint32_t aB = aBase + buf * ASTG;
        const uint32_t bB = bBase + buf * BSTG;
        #pragma unroll
        for (int s = 0; s < 4; s++) {
            uint32_t af[4][4], bf[8][2];
            #pragma unroll
            for (int fm = 0; fm < 4; fm++)
                ldsm4(af[fm][0], af[fm][1], af[fm][2], af[fm][3],
                      aB + fm * (16 * 144) + s * 32);
            #pragma unroll
            for (int cb = 0; cb < 4; cb++)
                ldsm4(bf[2*cb][0], bf[2*cb][1], bf[2*cb+1][0], bf[2*cb+1][1],
                      bB + cb * (16 * 144) + s * 32);
            #pragma unroll
            for (int fm = 0; fm < 4; fm++)
                #pragma unroll
                for (int fn = 0; fn < 8; fn++)
                    mma16(c[fm][fn], af[fm], bf[fn][0], bf[fn][1]);
        }
    }

    #pragma unroll
    for (int fm = 0; fm < 4; fm++) {
        #pragma unroll
        for (int fn = 0; fn < 8; fn++) {
            const int m0 = row0 + wm + fm * 16 + g;
            const int m1 = m0 + 8;
            const int n  = col0 + wn + fn * 8 + 2 * tg;
            const float b0v = bias[n], b1v = bias[n + 1];
            float2 lo = make_float2(c[fm][fn].x + b0v, c[fm][fn].y + b1v);
            float2 hi = make_float2(c[fm][fn].z + b0v, c[fm][fn].w + b1v);
            if (MODE == 0) {
                const int which = n >> 10, cc = n & 1023, h = cc >> 6, d = cc & 63;
                const int b = m0 >> 11, t = m0 & 2047;   // same b for m0, m1
                if (which < 2) {
                    __half* dst = (which == 0) ? g_q : g_k;
                    *(__half2*)&dst[((size_t)((b * HH + h) * TT + t)) * DHD + d] =
                        __floats2half2_rn(lo.x, lo.y);
                    *(__half2*)&dst[((size_t)((b * HH + h) * TT + t + 8)) * DHD + d] =
                        __floats2half2_rn(hi.x, hi.y);
                } else {
                    __half* dst = g_vt + (size_t)(b * HH + h) * DHD * TT;
                    dst[(size_t)d * TT + t]           = __float2half_rn(lo.x);
                    dst[(size_t)(d + 1) * TT + t]     = __float2half_rn(lo.y);
                    dst[(size_t)d * TT + t + 8]       = __float2half_rn(hi.x);
                    dst[(size_t)(d + 1) * TT + t + 8] = __float2half_rn(hi.y);
                }
            } else {
                *(float2*)&Out[(size_t)m0 * N + n] = lo;
                *(float2*)&Out[(size_t)m1 * N + n] = hi;
            }
        }
    }
}

// ---------------------------------------------------------------------------
// f16 tensor-core causal flash attention, 128-key tiles, 2-stage cp.async ring.
// CTA = (bh, 64-row q tile), 4 warps x m16. P@V done in two 64-key halves so
// P aliases the Q buffer. K rows 144 B, V^T rows 272 B (both conflict-free).
// ---------------------------------------------------------------------------
#define QB  9216      // Q tile: 64 x 144 B
#define KTB 18432     // K tile: 128 rows x 144 B
#define VTB 17408     // V^T tile: 64 rows x 272 B
#define SCL2E 0.1803368801111204f   // (1/8) * log2(e)

__global__ __launch_bounds__(128)
void attn_kernel()
{
    extern __shared__ __align__(16) char smc[];
    __half* Ps = (__half*)smc;                  // aliases Q (rows 72 halves)
    const uint32_t sQ = smem_u32(smc);
    const uint32_t sK = sQ + QB;                // 2 x KTB
    const uint32_t sV = sK + 2 * KTB;           // 2 x VTB

    const int bh = blockIdx.y;
    const int qt = (int)gridDim.x - 1 - (int)blockIdx.x;  // big tiles first
    const int q0 = qt * 64;
    const int tid = threadIdx.x, lane = tid & 31, wid = tid >> 5;
    const int wm = wid * 16;
    const int g = lane >> 2, tg = lane & 3;

    const __half* Qg = g_q  + (size_t)bh * TT * DHD;
    const __half* Kg = g_k  + (size_t)bh * TT * DHD;
    const __half* Vg = g_vt + (size_t)bh * DHD * TT;

    auto issueKV = [&](int kt, int buf) {
        const int k0 = kt * 128;
        // K: 128 rows x 8 chunks = 1024 cp16 over 128 threads
        #pragma unroll
        for (int i = 0; i < 8; i++) {
            int idx = tid + i * 128;
            int r = idx >> 3, c8 = idx & 7;
            cp16(sK + buf * KTB + r * 144 + c8 * 16,
                 Kg + (size_t)(k0 + r) * DHD + c8 * 8);
        }
        // V^T: 64 rows x 16 chunks = 1024 cp16 over 128 threads
        #pragma unroll
        for (int i = 0; i < 8; i++) {
            int idx = tid + i * 128;
            int r = idx >> 4, c16 = idx & 15;
            cp16(sV + buf * VTB + r * 272 + c16 * 16,
                 Vg + (size_t)r * TT + k0 + c16 * 8);
        }
        cp_commit();
    };

    const int NT = (qt + 2) >> 1;   // ceil(64*(qt+1)/128)

    // prologue: Q + KV0 (group 0), KV1 (group 1; keys [128,256) always exist)
    #pragma unroll
    for (int i = 0; i < 4; i++) {
        int idx = tid + i * 128;
        int r = idx >> 3, c8 = idx & 7;
        cp16(sQ + r * 144 + c8 * 16, Qg + (size_t)(q0 + r) * DHD + c8 * 8);
    }
    issueKV(0, 0);   // commits Q too (same group)
    issueKV(1, 1);

    // ldmatrix bases
    const uint32_t aQ = sQ + (wm + (lane & 15)) * 144 + (lane >> 4) * 16;
    const uint32_t kOffK = (((lane >> 4) << 3) + (lane & 7)) * 144
                         + ((lane >> 3) & 1) * 16;
    const uint32_t kOffV = (((lane >> 4) << 3) + (lane & 7)) * 272
                         + ((lane >> 3) & 1) * 16;
    const uint32_t aP = aQ;   // Ps aliases Qs

    uint32_t qf[4][4];
    float4 o[8];
    #pragma unroll
    for (int fn = 0; fn < 8; fn++) o[fn] = make_float4(0.f, 0.f, 0.f, 0.f);
    float m0 = -INFINITY, m1 = -INFINITY, l0 = 0.f, l1 = 0.f;
    const int r0g = q0 + wm + g, r1g = r0g + 8;

    for (int kt = 0; kt < NT; kt++) {
        const int k0 = kt * 128;
        if (kt + 1 < NT) cp_wait<1>();
        else             cp_wait<0>();
        __syncthreads();

        if (kt == 0) {
            #pragma unroll
            for (int kc = 0; kc < 4; kc++)
                ldsm4(qf[kc][0], qf[kc][1], qf[kc][2], qf[kc][3], aQ + kc * 32);
        }

        const int buf = kt & 1;
        const uint32_t bK = sK + buf * KTB + kOffK;
        const uint32_t bV = sV + buf * VTB + kOffV;

        // S = Q K^T  (m16 x n128), raw scores
        float4 s[16];
        #pragma unroll
        for (int fn = 0; fn < 16; fn++) s[fn] = make_float4(0.f, 0.f, 0.f, 0.f);
        #pragma unroll
        for (int kc = 0; kc < 4; kc++) {
            #pragma unroll
            for (int cb = 0; cb < 8; cb++) {
                uint32_t b0, b1, b2, b3;
                ldsm4(b0, b1, b2, b3, bK + cb * (16 * 144) + kc * 32);
                mma16(s[2*cb],   qf[kc], b0, b1);
                mma16(s[2*cb+1], qf[kc], b2, b3);
            }
        }

        // causal mask (only the last tile can straddle the diagonal)
        if (kt == NT - 1) {
            #pragma unroll
            for (int fn = 0; fn < 16; fn++) {
                int c0 = k0 + fn * 8 + 2 * tg, c1 = c0 + 1;
                if (c0 > r0g) s[fn].x = -INFINITY;
                if (c1 > r0g) s[fn].y = -INFINITY;
                if (c0 > r1g) s[fn].z = -INFINITY;
                if (c1 > r1g) s[fn].w = -INFINITY;
            }
        }

        // online softmax in base-2 domain (rows g, g+8)
        float rmax0 = -INFINITY, rmax1 = -INFINITY;
        #pragma unroll
        for (int fn = 0; fn < 16; fn++) {
            rmax0 = fmaxf(rmax0, fmaxf(s[fn].x, s[fn].y));
            rmax1 = fmaxf(rmax1, fmaxf(s[fn].z, s[fn].w));
        }
        rmax0 = fmaxf(rmax0, __shfl_xor_sync(0xffffffffu, rmax0, 1));
        rmax0 = fmaxf(rmax0, __shfl_xor_sync(0xffffffffu, rmax0, 2));
        rmax1 = fmaxf(rmax1, __shfl_xor_sync(0xffffffffu, rmax1, 1));
        rmax1 = fmaxf(rmax1, __shfl_xor_sync(0xffffffffu, rmax1, 2));
        const float mn0 = fmaxf(m0, rmax0), mn1 = fmaxf(m1, rmax1);
        const float al0 = ex2((m0 - mn0) * SCL2E), al1 = ex2((m1 - mn1) * SCL2E);
        m0 = mn0; m1 = mn1;
        float rs0 = 0.f, rs1 = 0.f;
        #pragma unroll
        for (int fn = 0; fn < 16; fn++) {
            s[fn].x = ex2((s[fn].x - mn0) * SCL2E);
            s[fn].y = ex2((s[fn].y - mn0) * SCL2E);
            s[fn].z = ex2((s[fn].z - mn1) * SCL2E);
            s[fn].w = ex2((s[fn].w - mn1) * SCL2E);
            rs0 += s[fn].x + s[fn].y;
            rs1 += s[fn].z + s[fn].w;
        }
        rs0 += __shfl_xor_sync(0xffffffffu, rs0, 1);
        rs0 += __shfl_xor_sync(0xffffffffu, rs0, 2);
        rs1 += __shfl_xor_sync(0xffffffffu, rs1, 1);
        rs1 += __shfl_xor_sync(0xffffffffu, rs1, 2);
        l0 = l0 * al0 + rs0;
        l1 = l1 * al1 + rs1;
        #pragma unroll
        for (int fn = 0; fn < 8; fn++) {
            o[fn].x *= al0; o[fn].y *= al0;
            o[fn].z *= al1; o[fn].w *= al1;
        }

        // O += P @ V in two 64-key halves (P reuses the Q-buffer rows)
        #pragma unroll
        for (int h = 0; h < 2; h++) {
            __syncwarp();
            #pragma unroll
            for (int j = 0; j < 8; j++) {
                const int fn = 8 * h + j;
                *(__half2*)&Ps[(wm + g) * 72 + j * 8 + 2 * tg] =
                    __floats2half2_rn(s[fn].x, s[fn].y);
                *(__half2*)&Ps[(wm + g + 8) * 72 + j * 8 + 2 * tg] =
                    __floats2half2_rn(s[fn].z, s[fn].w);
            }
            __syncwarp();
            #pragma unroll
            for (int kc = 0; kc < 4; kc++) {
                uint32_t pf[4];
                ldsm4(pf[0], pf[1], pf[2], pf[3], aP + kc * 32);
                #pragma unroll
                for (int cb = 0; cb < 4; cb++) {
                    uint32_t b0, b1, b2, b3;
                    ldsm4(b0, b1, b2, b3,
                          bV + cb * (16 * 272) + (4 * h + kc) * 32);
                    mma16(o[2*cb],   pf, b0, b1);
                    mma16(o[2*cb+1], pf, b2, b3);
                }
            }
        }

        // free this buffer for kt+2, then prefetch
        __syncthreads();
        if (kt + 2 < NT) issueKV(kt + 2, buf);
    }

    // finalize -> g_ao (f16), token-major
    const int b = bh >> 4, h = bh & 15;
    const float inv0 = 1.f / l0, inv1 = 1.f / l1;
    #pragma unroll
    for (int fn = 0; fn < 8; fn++) {
        const int d = fn * 8 + 2 * tg;
        *(__half2*)&g_ao[(size_t)(b * TT + r0g) * CC + h * 64 + d] =
            __floats2half2_rn(o[fn].x * inv0, o[fn].y * inv0);
        *(__half2*)&g_ao[(size_t)(b * TT + r1g) * CC + h * 64 + d] =
            __floats2half2_rn(o[fn].z * inv1, o[fn].w * inv1);
    }
}

// ---------------------------------------------------------------------------
extern "C" void kernel_launch(void* const* d_in, const int* in_sizes, int n_in,
                              void* d_out, int out_size)
{
    const float* x      = (const float*)d_in[0];
    const float* W_qkv  = (const float*)d_in[1];
    const float* b_qkv  = (const float*)d_in[2];
    const float* W_proj = (const float*)d_in[3];
    const float* b_proj = (const float*)d_in[4];
    float* out = (float*)d_out;

    __half* xh;     cudaGetSymbolAddress((void**)&xh,     g_xh);
    __half* wqkvT;  cudaGetSymbolAddress((void**)&wqkvT,  g_wqkvT);
    __half* wprojT; cudaGetSymbolAddress((void**)&wprojT, g_wprojT);
    __half* ao;     cudaGetSymbolAddress((void**)&ao,     g_ao);

    // 0) convert x to f16; transpose+convert weights to f16
    cvt_f32_f16<<<(NTOK*CC/4 + 255)/256, 256>>>(x, xh, NTOK*CC/4);
    transpose_cvt_h<<<dim3(3*CC/32, CC/32), dim3(32, 8)>>>(W_qkv,  wqkvT,  CC, 3*CC);
    transpose_cvt_h<<<dim3(CC/32,   CC/32), dim3(32, 8)>>>(W_proj, wprojT, CC, CC);

    const int gemm_smem = 3 * (ASTG + BSTG);   // 165888
    cudaFuncSetAttribute(mma_gemm<0>, cudaFuncAttributeMaxDynamicSharedMemorySize,
                         gemm_smem);
    cudaFuncSetAttribute(mma_gemm<1>, cudaFuncAttributeMaxDynamicSharedMemorySize,
                         gemm_smem);

    // 1) QKV GEMM (f16 mma, 256x128 tiles, K-tile 64) + scatter
    mma_gemm<0><<<dim3(3*CC/128, NTOK/256), 256, gemm_smem>>>(xh, wqkvT, b_qkv,
                                                              nullptr, NTOK, 3*CC, CC);

    // 2) causal flash attention (f16 mma, 128-key tiles, ~79 KB smem/CTA)
    const int attn_smem = QB + 2 * (KTB + VTB);   // 80896
    cudaFuncSetAttribute(attn_kernel, cudaFuncAttributeMaxDynamicSharedMemorySize,
                         attn_smem);
    attn_kernel<<<dim3(TT/64, BB*HH), 128, attn_smem>>>();

    // 3) output projection (f16 mma, 256x128 tiles, K-tile 64)
    mma_gemm<1><<<dim3(CC/128, NTOK/256), 256, gemm_smem>>>(ao, wprojT, b_proj,
                                                            out, NTOK, CC, CC);
}

// round 12
// speedup vs baseline: 1.2589x; 1.0061x over previous
#include <cuda_runtime.h>
#include <cuda_fp16.h>
#include <math.h>
#include <stdint.h>

#define BB 2
#define TT 2048
#define CC 1024
#define HH 16
#define DHD 64
#define NTOK (BB*TT)   // 4096

// Scratch (allocation-free: __device__ globals)
__device__ __half g_xh[NTOK*CC];        // x as f16
__device__ __half g_q[BB*HH*TT*DHD];    // f16, [bh][t][d]
__device__ __half g_k[BB*HH*TT*DHD];    // f16, [bh][t][d]
__device__ __half g_vt[BB*HH*DHD*TT];   // f16, TRANSPOSED [bh][d][t]
__device__ __half g_ao[NTOK*CC];        // attention out f16, token-major
__device__ __half g_wqkvT[3*CC*CC];     // W_qkv^T f16, [3072][1024]
__device__ __half g_wprojT[CC*CC];      // W_proj^T f16, [1024][1024]

// ---------------------------------------------------------------------------
__device__ __forceinline__ float ex2(float x) {
    float r; asm("ex2.approx.f32 %0, %1;" : "=f"(r) : "f"(x)); return r;
}
__device__ __forceinline__ uint32_t smem_u32(const void* p) {
    return (uint32_t)__cvta_generic_to_shared(p);
}
__device__ __forceinline__ void ldsm4(uint32_t& r0, uint32_t& r1, uint32_t& r2,
                                      uint32_t& r3, uint32_t a) {
    asm volatile("ldmatrix.sync.aligned.m8n8.x4.shared.b16 {%0,%1,%2,%3},[%4];"
                 : "=r"(r0), "=r"(r1), "=r"(r2), "=r"(r3) : "r"(a));
}
// f16 MMA: D(f32) += A(f16 m16k16) * B(f16 k16n8)
__device__ __forceinline__ void mma16(float4& d, const uint32_t* a,
                                      uint32_t b0, uint32_t b1) {
    asm volatile("mma.sync.aligned.m16n8k16.row.col.f32.f16.f16.f32 "
                 "{%0,%1,%2,%3},{%4,%5,%6,%7},{%8,%9},{%0,%1,%2,%3};"
                 : "+f"(d.x), "+f"(d.y), "+f"(d.z), "+f"(d.w)
                 : "r"(a[0]), "r"(a[1]), "r"(a[2]), "r"(a[3]), "r"(b0), "r"(b1));
}
__device__ __forceinline__ void cp16(uint32_t s, const void* g) {
    asm volatile("cp.async.cg.shared.global [%0], [%1], 16;" :: "r"(s), "l"(g));
}
__device__ __forceinline__ void cp_commit() {
    asm volatile("cp.async.commit_group;");
}
template<int N>
__device__ __forceinline__ void cp_wait() {
    asm volatile("cp.async.wait_group %0;" :: "n"(N));
}

// ---------------------------------------------------------------------------
__global__ void cvt_f32_f16(const float* __restrict__ in, __half* __restrict__ out,
                            int n4)
{
    int i = blockIdx.x * blockDim.x + threadIdx.x;
    if (i < n4) {
        float4 v = ((const float4*)in)[i];
        __half2 h0 = __floats2half2_rn(v.x, v.y);
        __half2 h1 = __floats2half2_rn(v.z, v.w);
        ((uint2*)out)[i] = make_uint2(*(uint32_t*)&h0, *(uint32_t*)&h1);
    }
}

// Transpose + f16-convert: Wt[n*K + k] = f16(W[k*N + n])
__global__ void transpose_cvt_h(const float* __restrict__ W, __half* __restrict__ Wt,
                                int K, int N)
{
    __shared__ float tile[32][33];
    const int n0 = blockIdx.x * 32, k0 = blockIdx.y * 32;
    const int tx = threadIdx.x, ty = threadIdx.y;
    #pragma unroll
    for (int i = ty; i < 32; i += 8)
        tile[i][tx] = W[(size_t)(k0 + i) * N + n0 + tx];
    __syncthreads();
    #pragma unroll
    for (int i = ty; i < 32; i += 8)
        Wt[(size_t)(n0 + i) * K + k0 + tx] = __float2half_rn(tile[tx][i]);
}

// ---------------------------------------------------------------------------
// f16 tensor-core GEMM, 256x128 CTA tile, 256 threads (8 warps of 64x64),
// K-tile = 64 (four k16 sub-steps), 3-stage cp.async ring.
// Rows padded to 144 B (conflict-free LDSM: 144/4=36 = 4 mod 32).
// MODE 0: scatter into g_q/g_k (f16, [bh][t][d]) and g_vt (f16, [bh][d][t])
// MODE 1: fp32 epilogue into Out
// ---------------------------------------------------------------------------
#define ASTG 36864     // A stage: 256 rows x 144 B
#define BSTG 18432     // B stage: 128 rows x 144 B

template<int MODE>
__global__ __launch_bounds__(256, 1)
void mma_gemm(const __half* __restrict__ A, const __half* __restrict__ Bt,
              const float* __restrict__ bias, float* __restrict__ Out,
              int M, int N, int K)
{
    extern __shared__ __align__(16) char dsm[];
    const uint32_t sA = smem_u32(dsm);            // 3 stages A
    const uint32_t sB = sA + 3 * ASTG;            // 3 stages B

    const int row0 = blockIdx.y * 256, col0 = blockIdx.x * 128;
    const int tid = threadIdx.x, lane = tid & 31, wid = tid >> 5;
    const int wm = (wid >> 1) * 64, wn = (wid & 1) * 64;
    const int g = lane >> 2, tg = lane & 3;

    float4 c[4][8];
    #pragma unroll
    for (int i = 0; i < 4; i++)
        #pragma unroll
        for (int j = 0; j < 8; j++) c[i][j] = make_float4(0.f, 0.f, 0.f, 0.f);

    // ldmatrix bases: A m16k16 rows = m; B n8k16 rows = n
    const uint32_t aBase = sA + (wm + (lane & 15)) * 144 + (lane >> 4) * 16;
    const uint32_t bBase = sB + (wn + ((lane >> 4) << 3) + (lane & 7)) * 144
                              + ((lane >> 3) & 1) * 16;

    const int NKT = K / 64;   // 16

    auto issueAB = [&](int kt, int buf) {
        #pragma unroll
        for (int i = 0; i < 8; i++) {
            int idx = tid + i * 256;
            int r = idx >> 3, c8 = idx & 7;
            cp16(sA + buf * ASTG + r * 144 + c8 * 16,
                 A + (size_t)(row0 + r) * K + kt * 64 + c8 * 8);
        }
        #pragma unroll
        for (int i = 0; i < 4; i++) {
            int idx = tid + i * 256;
            int r = idx >> 3, c8 = idx & 7;
            cp16(sB + buf * BSTG + r * 144 + c8 * 16,
                 Bt + (size_t)(col0 + r) * K + kt * 64 + c8 * 8);
        }
        cp_commit();
    };

    issueAB(0, 0); issueAB(1, 1);

    for (int kt = 0; kt < NKT; kt++) {
        if (kt + 1 < NKT) cp_wait<1>();
        else              cp_wait<0>();
        __syncthreads();
        if (kt + 2 < NKT) issueAB(kt + 2, (kt + 2) % 3);

        const int buf = kt % 3;
        const uint32_t aB = aBase + buf * ASTG;
        const uint32_t bB = bBase + buf * BSTG;
        #pragma unroll
        for (int s = 0; s < 4; s++) {
            uint32_t af[4][4], bf[8][2];
            #pragma unroll
            for (int fm = 0; fm < 4; fm++)
                ldsm4(af[fm][0], af[fm][1], af[fm][2], af[fm][3],
                      aB + fm * (16 * 144) + s * 32);
            #pragma unroll
            for (int cb = 0; cb < 4; cb++)
                ldsm4(bf[2*cb][0], bf[2*cb][1], bf[2*cb+1][0], bf[2*cb+1][1],
                      bB + cb * (16 * 144) + s * 32);
            #pragma unroll
            for (int fm = 0; fm < 4; fm++)
                #pragma unroll
                for (int fn = 0; fn < 8; fn++)
                    mma16(c[fm][fn], af[fm], bf[fn][0], bf[fn][1]);
        }
    }

    #pragma unroll
    for (int fm = 0; fm < 4; fm++) {
        #pragma unroll
        for (int fn = 0; fn < 8; fn++) {
            const int m0 = row0 + wm + fm * 16 + g;
            const int m1 = m0 + 8;
            const int n  = col0 + wn + fn * 8 + 2 * tg;
            const float b0v = bias[n], b1v = bias[n + 1];
            float2 lo = make_float2(c[fm][fn].x + b0v, c[fm][fn].y + b1v);
            float2 hi = make_float2(c[fm][fn].z + b0v, c[fm][fn].w + b1v);
            if (MODE == 0) {
                const int which = n >> 10, cc = n & 1023, h = cc >> 6, d = cc & 63;
                const int b = m0 >> 11, t = m0 & 2047;   // same b for m0, m1
                if (which < 2) {
                    __half* dst = (which == 0) ? g_q : g_k;
                    *(__half2*)&dst[((size_t)((b * HH + h) * TT + t)) * DHD + d] =
                        __floats2half2_rn(lo.x, lo.y);
                    *(__half2*)&dst[((size_t)((b * HH + h) * TT + t + 8)) * DHD + d] =
                        __floats2half2_rn(hi.x, hi.y);
                } else {
                    __half* dst = g_vt + (size_t)(b * HH + h) * DHD * TT;
                    dst[(size_t)d * TT + t]           = __float2half_rn(lo.x);
                    dst[(size_t)(d + 1) * TT + t]     = __float2half_rn(lo.y);
                    dst[(size_t)d * TT + t + 8]       = __float2half_rn(hi.x);
                    dst[(size_t)(d + 1) * TT + t + 8] = __float2half_rn(hi.y);
                }
            } else {
                *(float2*)&Out[(size_t)m0 * N + n] = lo;
                *(float2*)&Out[(size_t)m1 * N + n] = hi;
            }
        }
    }
}

// ---------------------------------------------------------------------------
// f16 tensor-core causal flash attention, 128-row q tiles x 128-key tiles,
// 256 threads (8 warps x m16), 2-stage cp.async KV ring.
// q-tiles and key-tiles align on the diagonal: mask only on kt == qt.
// P@V in two 64-key halves so P aliases the Q buffer.
// K rows 144 B, V^T rows 272 B (both conflict-free for LDSM).
// ---------------------------------------------------------------------------
#define QB2 18432     // Q tile: 128 x 144 B
#define KTB 18432     // K tile: 128 rows x 144 B
#define VTB 17408     // V^T tile: 64 rows x 272 B
#define SCL2E 0.1803368801111204f   // (1/8) * log2(e)

__global__ __launch_bounds__(256)
void attn_kernel()
{
    extern __shared__ __align__(16) char smc[];
    __half* Ps = (__half*)smc;                  // aliases Q (rows 72 halves)
    const uint32_t sQ = smem_u32(smc);
    const uint32_t sK = sQ + QB2;               // 2 x KTB
    const uint32_t sV = sK + 2 * KTB;           // 2 x VTB

    const int bh = blockIdx.y;
    const int qt = (int)gridDim.x - 1 - (int)blockIdx.x;  // big tiles first
    const int q0 = qt * 128;
    const int tid = threadIdx.x, lane = tid & 31, wid = tid >> 5;
    const int wm = wid * 16;
    const int g = lane >> 2, tg = lane & 3;

    const __half* Qg = g_q  + (size_t)bh * TT * DHD;
    const __half* Kg = g_k  + (size_t)bh * TT * DHD;
    const __half* Vg = g_vt + (size_t)bh * DHD * TT;

    auto issueKV = [&](int kt, int buf) {
        const int k0 = kt * 128;
        // K: 128 rows x 8 chunks = 1024 cp16 over 256 threads
        #pragma unroll
        for (int i = 0; i < 4; i++) {
            int idx = tid + i * 256;
            int r = idx >> 3, c8 = idx & 7;
            cp16(sK + buf * KTB + r * 144 + c8 * 16,
                 Kg + (size_t)(k0 + r) * DHD + c8 * 8);
        }
        // V^T: 64 rows x 16 chunks = 1024 cp16 over 256 threads
        #pragma unroll
        for (int i = 0; i < 4; i++) {
            int idx = tid + i * 256;
            int r = idx >> 4, c16 = idx & 15;
            cp16(sV + buf * VTB + r * 272 + c16 * 16,
                 Vg + (size_t)r * TT + k0 + c16 * 8);
        }
        cp_commit();
    };

    const int NT = qt + 1;

    // prologue: Q + KV0 (group 0), KV1 (group 1; keys [128,256) always exist)
    #pragma unroll
    for (int i = 0; i < 4; i++) {
        int idx = tid + i * 256;
        int r = idx >> 3, c8 = idx & 7;
        cp16(sQ + r * 144 + c8 * 16, Qg + (size_t)(q0 + r) * DHD + c8 * 8);
    }
    issueKV(0, 0);   // commits Q too (same group)
    issueKV(1, 1);

    // ldmatrix bases
    const uint32_t aQ = sQ + (wm + (lane & 15)) * 144 + (lane >> 4) * 16;
    const uint32_t kOffK = (((lane >> 4) << 3) + (lane & 7)) * 144
                         + ((lane >> 3) & 1) * 16;
    const uint32_t kOffV = (((lane >> 4) << 3) + (lane & 7)) * 272
                         + ((lane >> 3) & 1) * 16;
    const uint32_t aP = aQ;   // Ps aliases Qs

    uint32_t qf[4][4];
    float4 o[8];
    #pragma unroll
    for (int fn = 0; fn < 8; fn++) o[fn] = make_float4(0.f, 0.f, 0.f, 0.f);
    float m0 = -INFINITY, m1 = -INFINITY, l0 = 0.f, l1 = 0.f;
    const int r0g = q0 + wm + g, r1g = r0g + 8;

    for (int kt = 0; kt < NT; kt++) {
        const int k0 = kt * 128;
        if (kt + 1 < NT) cp_wait<1>();
        else             cp_wait<0>();
        __syncthreads();

        if (kt == 0) {
            #pragma unroll
            for (int kc = 0; kc < 4; kc++)
                ldsm4(qf[kc][0], qf[kc][1], qf[kc][2], qf[kc][3], aQ + kc * 32);
        }

        const int buf = kt & 1;
        const uint32_t bK = sK + buf * KTB + kOffK;
        const uint32_t bV = sV + buf * VTB + kOffV;

        // S = Q K^T  (m16 x n128), raw scores
        float4 s[16];
        #pragma unroll
        for (int fn = 0; fn < 16; fn++) s[fn] = make_float4(0.f, 0.f, 0.f, 0.f);
        #pragma unroll
        for (int kc = 0; kc < 4; kc++) {
            #pragma unroll
            for (int cb = 0; cb < 8; cb++) {
                uint32_t b0, b1, b2, b3;
                ldsm4(b0, b1, b2, b3, bK + cb * (16 * 144) + kc * 32);
                mma16(s[2*cb],   qf[kc], b0, b1);
                mma16(s[2*cb+1], qf[kc], b2, b3);
            }
        }

        // causal mask — q tiles and key tiles align, so only kt == qt masks
        if (kt == NT - 1) {
            #pragma unroll
            for (int fn = 0; fn < 16; fn++) {
                int c0 = k0 + fn * 8 + 2 * tg, c1 = c0 + 1;
                if (c0 > r0g) s[fn].x = -INFINITY;
                if (c1 > r0g) s[fn].y = -INFINITY;
                if (c0 > r1g) s[fn].z = -INFINITY;
                if (c1 > r1g) s[fn].w = -INFINITY;
            }
        }

        // online softmax in base-2 domain (rows g, g+8)
        float rmax0 = -INFINITY, rmax1 = -INFINITY;
        #pragma unroll
        for (int fn = 0; fn < 16; fn++) {
            rmax0 = fmaxf(rmax0, fmaxf(s[fn].x, s[fn].y));
            rmax1 = fmaxf(rmax1, fmaxf(s[fn].z, s[fn].w));
        }
        rmax0 = fmaxf(rmax0, __shfl_xor_sync(0xffffffffu, rmax0, 1));
        rmax0 = fmaxf(rmax0, __shfl_xor_sync(0xffffffffu, rmax0, 2));
        rmax1 = fmaxf(rmax1, __shfl_xor_sync(0xffffffffu, rmax1, 1));
        rmax1 = fmaxf(rmax1, __shfl_xor_sync(0xffffffffu, rmax1, 2));
        const float mn0 = fmaxf(m0, rmax0), mn1 = fmaxf(m1, rmax1);
        const float al0 = ex2((m0 - mn0) * SCL2E), al1 = ex2((m1 - mn1) * SCL2E);
        m0 = mn0; m1 = mn1;
        float rs0 = 0.f, rs1 = 0.f;
        #pragma unroll
        for (int fn = 0; fn < 16; fn++) {
            s[fn].x = ex2((s[fn].x - mn0) * SCL2E);
            s[fn].y = ex2((s[fn].y - mn0) * SCL2E);
            s[fn].z = ex2((s[fn].z - mn1) * SCL2E);
            s[fn].w = ex2((s[fn].w - mn1) * SCL2E);
            rs0 += s[fn].x + s[fn].y;
            rs1 += s[fn].z + s[fn].w;
        }
        rs0 += __shfl_xor_sync(0xffffffffu, rs0, 1);
        rs0 += __shfl_xor_sync(0xffffffffu, rs0, 2);
        rs1 += __shfl_xor_sync(0xffffffffu, rs1, 1);
        rs1 += __shfl_xor_sync(0xffffffffu, rs1, 2);
        l0 = l0 * al0 + rs0;
        l1 = l1 * al1 + rs1;
        #pragma unroll
        for (int fn = 0; fn < 8; fn++) {
            o[fn].x *= al0; o[fn].y *= al0;
            o[fn].z *= al1; o[fn].w *= al1;
        }

        // O += P @ V in two 64-key halves (P reuses the Q-buffer rows)
        #pragma unroll
        for (int h = 0; h < 2; h++) {
            __syncwarp();
            #pragma unroll
            for (int j = 0; j < 8; j++) {
                const int fn = 8 * h + j;
                *(__half2*)&Ps[(wm + g) * 72 + j * 8 + 2 * tg] =
                    __floats2half2_rn(s[fn].x, s[fn].y);
                *(__half2*)&Ps[(wm + g + 8) * 72 + j * 8 + 2 * tg] =
                    __floats2half2_rn(s[fn].z, s[fn].w);
            }
            __syncwarp();
            #pragma unroll
            for (int kc = 0; kc < 4; kc++) {
                uint32_t pf[4];
                ldsm4(pf[0], pf[1], pf[2], pf[3], aP + kc * 32);
                #pragma unroll
                for (int cb = 0; cb < 4; cb++) {
                    uint32_t b0, b1, b2, b3;
                    ldsm4(b0, b1, b2, b3,
                          bV + cb * (16 * 272) + (4 * h + kc) * 32);
                    mma16(o[2*cb],   pf, b0, b1);
                    mma16(o[2*cb+1], pf, b2, b3);
                }
            }
        }

        // free this buffer for kt+2, then prefetch
        __syncthreads();
        if (kt + 2 < NT) issueKV(kt + 2, buf);
    }

    // finalize -> g_ao (f16), token-major
    const int b = bh >> 4, h = bh & 15;
    const float inv0 = 1.f / l0, inv1 = 1.f / l1;
    #pragma unroll
    for (int fn = 0; fn < 8; fn++) {
        const int d = fn * 8 + 2 * tg;
        *(__half2*)&g_ao[(size_t)(b * TT + r0g) * CC + h * 64 + d] =
            __floats2half2_rn(o[fn].x * inv0, o[fn].y * inv0);
        *(__half2*)&g_ao[(size_t)(b * TT + r1g) * CC + h * 64 + d] =
            __floats2half2_rn(o[fn].z * inv1, o[fn].w * inv1);
    }
}

// ---------------------------------------------------------------------------
extern "C" void kernel_launch(void* const* d_in, const int* in_sizes, int n_in,
                              void* d_out, int out_size)
{
    const float* x      = (const float*)d_in[0];
    const float* W_qkv  = (const float*)d_in[1];
    const float* b_qkv  = (const float*)d_in[2];
    const float* W_proj = (const float*)d_in[3];
    const float* b_proj = (const float*)d_in[4];
    float* out = (float*)d_out;

    __half* xh;     cudaGetSymbolAddress((void**)&xh,     g_xh);
    __half* wqkvT;  cudaGetSymbolAddress((void**)&wqkvT,  g_wqkvT);
    __half* wprojT; cudaGetSymbolAddress((void**)&wprojT, g_wprojT);
    __half* ao;     cudaGetSymbolAddress((void**)&ao,     g_ao);

    // 0) convert x to f16; transpose+convert weights to f16
    cvt_f32_f16<<<(NTOK*CC/4 + 255)/256, 256>>>(x, xh, NTOK*CC/4);
    transpose_cvt_h<<<dim3(3*CC/32, CC/32), dim3(32, 8)>>>(W_qkv,  wqkvT,  CC, 3*CC);
    transpose_cvt_h<<<dim3(CC/32,   CC/32), dim3(32, 8)>>>(W_proj, wprojT, CC, CC);

    const int gemm_smem = 3 * (ASTG + BSTG);   // 165888
    cudaFuncSetAttribute(mma_gemm<0>, cudaFuncAttributeMaxDynamicSharedMemorySize,
                         gemm_smem);
    cudaFuncSetAttribute(mma_gemm<1>, cudaFuncAttributeMaxDynamicSharedMemorySize,
                         gemm_smem);

    // 1) QKV GEMM (f16 mma, 256x128 tiles, K-tile 64) + scatter
    mma_gemm<0><<<dim3(3*CC/128, NTOK/256), 256, gemm_smem>>>(xh, wqkvT, b_qkv,
                                                              nullptr, NTOK, 3*CC, CC);

    // 2) causal flash attention (128-row q tiles, 256 threads, ~88 KB smem/CTA)
    const int attn_smem = QB2 + 2 * (KTB + VTB);   // 90112
    cudaFuncSetAttribute(attn_kernel, cudaFuncAttributeMaxDynamicSharedMemorySize,
                         attn_smem);
    attn_kernel<<<dim3(TT/128, BB*HH), 256, attn_smem>>>();

    // 3) output projection (f16 mma, 256x128 tiles, K-tile 64)
    mma_gemm<1><<<dim3(CC/128, NTOK/256), 256, gemm_smem>>>(ao, wprojT, b_proj,
                                                            out, NTOK, CC, CC);
}

// round 13
// speedup vs baseline: 1.2945x; 1.0283x over previous
#include <cuda_runtime.h>
#include <cuda_fp16.h>
#include <math.h>
#include <stdint.h>

#define BB 2
#define TT 2048
#define CC 1024
#define HH 16
#define DHD 64
#define NTOK (BB*TT)   // 4096

// Scratch (allocation-free: __device__ globals)
__device__ __half g_xh[NTOK*CC];        // x as f16
__device__ __half g_q[BB*HH*TT*DHD];    // f16, [bh][t][d]
__device__ __half g_k[BB*HH*TT*DHD];    // f16, [bh][t][d]
__device__ __half g_vt[BB*HH*DHD*TT];   // f16, TRANSPOSED [bh][d][t]
__device__ __half g_ao[NTOK*CC];        // attention out f16, token-major
__device__ __half g_wqkvT[3*CC*CC];     // W_qkv^T f16, [3072][1024]
__device__ __half g_wprojT[CC*CC];      // W_proj^T f16, [1024][1024]

// ---------------------------------------------------------------------------
__device__ __forceinline__ float ex2(float x) {
    float r; asm("ex2.approx.f32 %0, %1;" : "=f"(r) : "f"(x)); return r;
}
__device__ __forceinline__ uint32_t smem_u32(const void* p) {
    return (uint32_t)__cvta_generic_to_shared(p);
}
__device__ __forceinline__ void ldsm4(uint32_t& r0, uint32_t& r1, uint32_t& r2,
                                      uint32_t& r3, uint32_t a) {
    asm volatile("ldmatrix.sync.aligned.m8n8.x4.shared.b16 {%0,%1,%2,%3},[%4];"
                 : "=r"(r0), "=r"(r1), "=r"(r2), "=r"(r3) : "r"(a));
}
// f16 MMA: D(f32) += A(f16 m16k16) * B(f16 k16n8)
__device__ __forceinline__ void mma16(float4& d, const uint32_t* a,
                                      uint32_t b0, uint32_t b1) {
    asm volatile("mma.sync.aligned.m16n8k16.row.col.f32.f16.f16.f32 "
                 "{%0,%1,%2,%3},{%4,%5,%6,%7},{%8,%9},{%0,%1,%2,%3};"
                 : "+f"(d.x), "+f"(d.y), "+f"(d.z), "+f"(d.w)
                 : "r"(a[0]), "r"(a[1]), "r"(a[2]), "r"(a[3]), "r"(b0), "r"(b1));
}
__device__ __forceinline__ void cp16(uint32_t s, const void* g) {
    asm volatile("cp.async.cg.shared.global [%0], [%1], 16;" :: "r"(s), "l"(g));
}
__device__ __forceinline__ void cp_commit() {
    asm volatile("cp.async.commit_group;");
}
template<int N>
__device__ __forceinline__ void cp_wait() {
    asm volatile("cp.async.wait_group %0;" :: "n"(N));
}

// ---------------------------------------------------------------------------
__global__ void cvt_f32_f16(const float* __restrict__ in, __half* __restrict__ out,
                            int n4)
{
    int i = blockIdx.x * blockDim.x + threadIdx.x;
    if (i < n4) {
        float4 v = ((const float4*)in)[i];
        __half2 h0 = __floats2half2_rn(v.x, v.y);
        __half2 h1 = __floats2half2_rn(v.z, v.w);
        ((uint2*)out)[i] = make_uint2(*(uint32_t*)&h0, *(uint32_t*)&h1);
    }
}

// Transpose + f16-convert: Wt[n*K + k] = f16(W[k*N + n])
__global__ void transpose_cvt_h(const float* __restrict__ W, __half* __restrict__ Wt,
                                int K, int N)
{
    __shared__ float tile[32][33];
    const int n0 = blockIdx.x * 32, k0 = blockIdx.y * 32;
    const int tx = threadIdx.x, ty = threadIdx.y;
    #pragma unroll
    for (int i = ty; i < 32; i += 8)
        tile[i][tx] = W[(size_t)(k0 + i) * N + n0 + tx];
    __syncthreads();
    #pragma unroll
    for (int i = ty; i < 32; i += 8)
        Wt[(size_t)(n0 + i) * K + k0 + tx] = __float2half_rn(tile[tx][i]);
}

// ---------------------------------------------------------------------------
// f16 tensor-core GEMM, 256x128 CTA tile, 512 threads (16 warps of 64x32),
// K-tile = 64 (four k16 sub-steps), 3-stage cp.async ring.
// Rows padded to 144 B (conflict-free LDSM: 144/4=36 = 4 mod 32).
// MODE 0: scatter into g_q/g_k (f16, [bh][t][d]) and g_vt (f16, [bh][d][t])
// MODE 1: fp32 epilogue into Out
// ---------------------------------------------------------------------------
#define ASTG 36864     // A stage: 256 rows x 144 B
#define BSTG 18432     // B stage: 128 rows x 144 B

template<int MODE>
__global__ __launch_bounds__(512, 1)
void mma_gemm(const __half* __restrict__ A, const __half* __restrict__ Bt,
              const float* __restrict__ bias, float* __restrict__ Out,
              int M, int N, int K)
{
    extern __shared__ __align__(16) char dsm[];
    const uint32_t sA = smem_u32(dsm);            // 3 stages A
    const uint32_t sB = sA + 3 * ASTG;            // 3 stages B

    const int row0 = blockIdx.y * 256, col0 = blockIdx.x * 128;
    const int tid = threadIdx.x, lane = tid & 31, wid = tid >> 5;
    const int wm = (wid >> 2) * 64, wn = (wid & 3) * 32;
    const int g = lane >> 2, tg = lane & 3;

    float4 c[4][4];
    #pragma unroll
    for (int i = 0; i < 4; i++)
        #pragma unroll
        for (int j = 0; j < 4; j++) c[i][j] = make_float4(0.f, 0.f, 0.f, 0.f);

    // ldmatrix bases: A m16k16 rows = m; B n8k16 rows = n
    const uint32_t aBase = sA + (wm + (lane & 15)) * 144 + (lane >> 4) * 16;
    const uint32_t bBase = sB + (wn + ((lane >> 4) << 3) + (lane & 7)) * 144
                              + ((lane >> 3) & 1) * 16;

    const int NKT = K / 64;   // 16

    auto issueAB = [&](int kt, int buf) {
        // A: 256 rows x 8 chunks = 2048 cp16 over 512 threads
        #pragma unroll
        for (int i = 0; i < 4; i++) {
            int idx = tid + i * 512;
            int r = idx >> 3, c8 = idx & 7;
            cp16(sA + buf * ASTG + r * 144 + c8 * 16,
                 A + (size_t)(row0 + r) * K + kt * 64 + c8 * 8);
        }
        // B: 128 rows x 8 chunks = 1024 cp16 over 512 threads
        #pragma unroll
        for (int i = 0; i < 2; i++) {
            int idx = tid + i * 512;
            int r = idx >> 3, c8 = idx & 7;
            cp16(sB + buf * BSTG + r * 144 + c8 * 16,
                 Bt + (size_t)(col0 + r) * K + kt * 64 + c8 * 8);
        }
        cp_commit();
    };

    issueAB(0, 0); issueAB(1, 1);

    for (int kt = 0; kt < NKT; kt++) {
        if (kt + 1 < NKT) cp_wait<1>();
        else              cp_wait<0>();
        __syncthreads();
        if (kt + 2 < NKT) issueAB(kt + 2, (kt + 2) % 3);

        const int buf = kt % 3;
        const uint32_t aB = aBase + buf * ASTG;
        const uint32_t bB = bBase + buf * BSTG;
        #pragma unroll
        for (int s = 0; s < 4; s++) {
            uint32_t af[4][4], bf[4][2];
            #pragma unroll
            for (int fm = 0; fm < 4; fm++)
                ldsm4(af[fm][0], af[fm][1], af[fm][2], af[fm][3],
                      aB + fm * (16 * 144) + s * 32);
            #pragma unroll
            for (int cb = 0; cb < 2; cb++)
                ldsm4(bf[2*cb][0], bf[2*cb][1], bf[2*cb+1][0], bf[2*cb+1][1],
                      bB + cb * (16 * 144) + s * 32);
            #pragma unroll
            for (int fm = 0; fm < 4; fm++)
                #pragma unroll
                for (int fn = 0; fn < 4; fn++)
                    mma16(c[fm][fn], af[fm], bf[fn][0], bf[fn][1]);
        }
    }

    #pragma unroll
    for (int fm = 0; fm < 4; fm++) {
        #pragma unroll
        for (int fn = 0; fn < 4; fn++) {
            const int m0 = row0 + wm + fm * 16 + g;
            const int m1 = m0 + 8;
            const int n  = col0 + wn + fn * 8 + 2 * tg;
            const float b0v = bias[n], b1v = bias[n + 1];
            float2 lo = make_float2(c[fm][fn].x + b0v, c[fm][fn].y + b1v);
            float2 hi = make_float2(c[fm][fn].z + b0v, c[fm][fn].w + b1v);
            if (MODE == 0) {
                const int which = n >> 10, cc = n & 1023, h = cc >> 6, d = cc & 63;
                const int b = m0 >> 11, t = m0 & 2047;   // same b for m0, m1
                if (which < 2) {
                    __half* dst = (which == 0) ? g_q : g_k;
                    *(__half2*)&dst[((size_t)((b * HH + h) * TT + t)) * DHD + d] =
                        __floats2half2_rn(lo.x, lo.y);
                    *(__half2*)&dst[((size_t)((b * HH + h) * TT + t + 8)) * DHD + d] =
                        __floats2half2_rn(hi.x, hi.y);
                } else {
                    __half* dst = g_vt + (size_t)(b * HH + h) * DHD * TT;
                    dst[(size_t)d * TT + t]           = __float2half_rn(lo.x);
                    dst[(size_t)(d + 1) * TT + t]     = __float2half_rn(lo.y);
                    dst[(size_t)d * TT + t + 8]       = __float2half_rn(hi.x);
                    dst[(size_t)(d + 1) * TT + t + 8] = __float2half_rn(hi.y);
                }
            } else {
                *(float2*)&Out[(size_t)m0 * N + n] = lo;
                *(float2*)&Out[(size_t)m1 * N + n] = hi;
            }
        }
    }
}

// ---------------------------------------------------------------------------
// f16 tensor-core causal flash attention, 128-row q tiles x 128-key tiles,
// 256 threads (8 warps x m16), 2-stage cp.async KV ring.
// q-tiles and key-tiles align on the diagonal: mask only on kt == qt.
// P@V in two 64-key halves so P aliases the Q buffer.
// K rows 144 B, V^T rows 272 B (both conflict-free for LDSM).
// ---------------------------------------------------------------------------
#define QB2 18432     // Q tile: 128 x 144 B
#define KTB 18432     // K tile: 128 rows x 144 B
#define VTB 17408     // V^T tile: 64 rows x 272 B
#define SCL2E 0.1803368801111204f   // (1/8) * log2(e)

__global__ __launch_bounds__(256)
void attn_kernel()
{
    extern __shared__ __align__(16) char smc[];
    __half* Ps = (__half*)smc;                  // aliases Q (rows 72 halves)
    const uint32_t sQ = smem_u32(smc);
    const uint32_t sK = sQ + QB2;               // 2 x KTB
    const uint32_t sV = sK + 2 * KTB;           // 2 x VTB

    const int bh = blockIdx.y;
    const int qt = (int)gridDim.x - 1 - (int)blockIdx.x;  // big tiles first
    const int q0 = qt * 128;
    const int tid = threadIdx.x, lane = tid & 31, wid = tid >> 5;
    const int wm = wid * 16;
    const int g = lane >> 2, tg = lane & 3;

    const __half* Qg = g_q  + (size_t)bh * TT * DHD;
    const __half* Kg = g_k  + (size_t)bh * TT * DHD;
    const __half* Vg = g_vt + (size_t)bh * DHD * TT;

    auto issueKV = [&](int kt, int buf) {
        const int k0 = kt * 128;
        #pragma unroll
        for (int i = 0; i < 4; i++) {
            int idx = tid + i * 256;
            int r = idx >> 3, c8 = idx & 7;
            cp16(sK + buf * KTB + r * 144 + c8 * 16,
                 Kg + (size_t)(k0 + r) * DHD + c8 * 8);
        }
        #pragma unroll
        for (int i = 0; i < 4; i++) {
            int idx = tid + i * 256;
            int r = idx >> 4, c16 = idx & 15;
            cp16(sV + buf * VTB + r * 272 + c16 * 16,
                 Vg + (size_t)r * TT + k0 + c16 * 8);
        }
        cp_commit();
    };

    const int NT = qt + 1;

    // prologue: Q + KV0 (group 0), KV1 (group 1; keys [128,256) always exist)
    #pragma unroll
    for (int i = 0; i < 4; i++) {
        int idx = tid + i * 256;
        int r = idx >> 3, c8 = idx & 7;
        cp16(sQ + r * 144 + c8 * 16, Qg + (size_t)(q0 + r) * DHD + c8 * 8);
    }
    issueKV(0, 0);   // commits Q too (same group)
    issueKV(1, 1);

    // ldmatrix bases
    const uint32_t aQ = sQ + (wm + (lane & 15)) * 144 + (lane >> 4) * 16;
    const uint32_t kOffK = (((lane >> 4) << 3) + (lane & 7)) * 144
                         + ((lane >> 3) & 1) * 16;
    const uint32_t kOffV = (((lane >> 4) << 3) + (lane & 7)) * 272
                         + ((lane >> 3) & 1) * 16;
    const uint32_t aP = aQ;   // Ps aliases Qs

    uint32_t qf[4][4];
    float4 o[8];
    #pragma unroll
    for (int fn = 0; fn < 8; fn++) o[fn] = make_float4(0.f, 0.f, 0.f, 0.f);
    float m0 = -INFINITY, m1 = -INFINITY, l0 = 0.f, l1 = 0.f;
    const int r0g = q0 + wm + g, r1g = r0g + 8;

    for (int kt = 0; kt < NT; kt++) {
        const int k0 = kt * 128;
        if (kt + 1 < NT) cp_wait<1>();
        else             cp_wait<0>();
        __syncthreads();

        if (kt == 0) {
            #pragma unroll
            for (int kc = 0; kc < 4; kc++)
                ldsm4(qf[kc][0], qf[kc][1], qf[kc][2], qf[kc][3], aQ + kc * 32);
        }

        const int buf = kt & 1;
        const uint32_t bK = sK + buf * KTB + kOffK;
        const uint32_t bV = sV + buf * VTB + kOffV;

        // S = Q K^T  (m16 x n128), raw scores
        float4 s[16];
        #pragma unroll
        for (int fn = 0; fn < 16; fn++) s[fn] = make_float4(0.f, 0.f, 0.f, 0.f);
        #pragma unroll
        for (int kc = 0; kc < 4; kc++) {
            #pragma unroll
            for (int cb = 0; cb < 8; cb++) {
                uint32_t b0, b1, b2, b3;
                ldsm4(b0, b1, b2, b3, bK + cb * (16 * 144) + kc * 32);
                mma16(s[2*cb],   qf[kc], b0, b1);
                mma16(s[2*cb+1], qf[kc], b2, b3);
            }
        }

        // causal mask — q tiles and key tiles align, so only kt == qt masks
        if (kt == NT - 1) {
            #pragma unroll
            for (int fn = 0; fn < 16; fn++) {
                int c0 = k0 + fn * 8 + 2 * tg, c1 = c0 + 1;
                if (c0 > r0g) s[fn].x = -INFINITY;
                if (c1 > r0g) s[fn].y = -INFINITY;
                if (c0 > r1g) s[fn].z = -INFINITY;
                if (c1 > r1g) s[fn].w = -INFINITY;
            }
        }

        // online softmax in base-2 domain (rows g, g+8)
        float rmax0 = -INFINITY, rmax1 = -INFINITY;
        #pragma unroll
        for (int fn = 0; fn < 16; fn++) {
            rmax0 = fmaxf(rmax0, fmaxf(s[fn].x, s[fn].y));
            rmax1 = fmaxf(rmax1, fmaxf(s[fn].z, s[fn].w));
        }
        rmax0 = fmaxf(rmax0, __shfl_xor_sync(0xffffffffu, rmax0, 1));
        rmax0 = fmaxf(rmax0, __shfl_xor_sync(0xffffffffu, rmax0, 2));
        rmax1 = fmaxf(rmax1, __shfl_xor_sync(0xffffffffu, rmax1, 1));
        rmax1 = fmaxf(rmax1, __shfl_xor_sync(0xffffffffu, rmax1, 2));
        const float mn0 = fmaxf(m0, rmax0), mn1 = fmaxf(m1, rmax1);
        const float al0 = ex2((m0 - mn0) * SCL2E), al1 = ex2((m1 - mn1) * SCL2E);
        m0 = mn0; m1 = mn1;
        float rs0 = 0.f, rs1 = 0.f;
        #pragma unroll
        for (int fn = 0; fn < 16; fn++) {
            s[fn].x = ex2((s[fn].x - mn0) * SCL2E);
            s[fn].y = ex2((s[fn].y - mn0) * SCL2E);
            s[fn].z = ex2((s[fn].z - mn1) * SCL2E);
            s[fn].w = ex2((s[fn].w - mn1) * SCL2E);
            rs0 += s[fn].x + s[fn].y;
            rs1 += s[fn].z + s[fn].w;
        }
        rs0 += __shfl_xor_sync(0xffffffffu, rs0, 1);
        rs0 += __shfl_xor_sync(0xffffffffu, rs0, 2);
        rs1 += __shfl_xor_sync(0xffffffffu, rs1, 1);
        rs1 += __shfl_xor_sync(0xffffffffu, rs1, 2);
        l0 = l0 * al0 + rs0;
        l1 = l1 * al1 + rs1;
        #pragma unroll
        for (int fn = 0; fn < 8; fn++) {
            o[fn].x *= al0; o[fn].y *= al0;
            o[fn].z *= al1; o[fn].w *= al1;
        }

        // O += P @ V in two 64-key halves (P reuses the Q-buffer rows)
        #pragma unroll
        for (int h = 0; h < 2; h++) {
            __syncwarp();
            #pragma unroll
            for (int j = 0; j < 8; j++) {
                const int fn = 8 * h + j;
                *(__half2*)&Ps[(wm + g) * 72 + j * 8 + 2 * tg] =
                    __floats2half2_rn(s[fn].x, s[fn].y);
                *(__half2*)&Ps[(wm + g + 8) * 72 + j * 8 + 2 * tg] =
                    __floats2half2_rn(s[fn].z, s[fn].w);
            }
            __syncwarp();
            #pragma unroll
            for (int kc = 0; kc < 4; kc++) {
                uint32_t pf[4];
                ldsm4(pf[0], pf[1], pf[2], pf[3], aP + kc * 32);
                #pragma unroll
                for (int cb = 0; cb < 4; cb++) {
                    uint32_t b0, b1, b2, b3;
                    ldsm4(b0, b1, b2, b3,
                          bV + cb * (16 * 272) + (4 * h + kc) * 32);
                    mma16(o[2*cb],   pf, b0, b1);
                    mma16(o[2*cb+1], pf, b2, b3);
                }
            }
        }

        // free this buffer for kt+2, then prefetch
        __syncthreads();
        if (kt + 2 < NT) issueKV(kt + 2, buf);
    }

    // finalize -> g_ao (f16), token-major
    const int b = bh >> 4, h = bh & 15;
    const float inv0 = 1.f / l0, inv1 = 1.f / l1;
    #pragma unroll
    for (int fn = 0; fn < 8; fn++) {
        const int d = fn * 8 + 2 * tg;
        *(__half2*)&g_ao[(size_t)(b * TT + r0g) * CC + h * 64 + d] =
            __floats2half2_rn(o[fn].x * inv0, o[fn].y * inv0);
        *(__half2*)&g_ao[(size_t)(b * TT + r1g) * CC + h * 64 + d] =
            __floats2half2_rn(o[fn].z * inv1, o[fn].w * inv1);
    }
}

// ---------------------------------------------------------------------------
extern "C" void kernel_launch(void* const* d_in, const int* in_sizes, int n_in,
                              void* d_out, int out_size)
{
    const float* x      = (const float*)d_in[0];
    const float* W_qkv  = (const float*)d_in[1];
    const float* b_qkv  = (const float*)d_in[2];
    const float* W_proj = (const float*)d_in[3];
    const float* b_proj = (const float*)d_in[4];
    float* out = (float*)d_out;

    __half* xh;     cudaGetSymbolAddress((void**)&xh,     g_xh);
    __half* wqkvT;  cudaGetSymbolAddress((void**)&wqkvT,  g_wqkvT);
    __half* wprojT; cudaGetSymbolAddress((void**)&wprojT, g_wprojT);
    __half* ao;     cudaGetSymbolAddress((void**)&ao,     g_ao);

    // 0) convert x to f16; transpose+convert weights to f16
    cvt_f32_f16<<<(NTOK*CC/4 + 255)/256, 256>>>(x, xh, NTOK*CC/4);
    transpose_cvt_h<<<dim3(3*CC/32, CC/32), dim3(32, 8)>>>(W_qkv,  wqkvT,  CC, 3*CC);
    transpose_cvt_h<<<dim3(CC/32,   CC/32), dim3(32, 8)>>>(W_proj, wprojT, CC, CC);

    const int gemm_smem = 3 * (ASTG + BSTG);   // 165888
    cudaFuncSetAttribute(mma_gemm<0>, cudaFuncAttributeMaxDynamicSharedMemorySize,
                         gemm_smem);
    cudaFuncSetAttribute(mma_gemm<1>, cudaFuncAttributeMaxDynamicSharedMemorySize,
                         gemm_smem);

    // 1) QKV GEMM (f16 mma, 256x128 tiles, 512 threads) + scatter
    mma_gemm<0><<<dim3(3*CC/128, NTOK/256), 512, gemm_smem>>>(xh, wqkvT, b_qkv,
                                                              nullptr, NTOK, 3*CC, CC);

    // 2) causal flash attention (128-row q tiles, 256 threads, ~88 KB smem/CTA)
    const int attn_smem = QB2 + 2 * (KTB + VTB);   // 90112
    cudaFuncSetAttribute(attn_kernel, cudaFuncAttributeMaxDynamicSharedMemorySize,
                         attn_smem);
    attn_kernel<<<dim3(TT/128, BB*HH), 256, attn_smem>>>();

    // 3) output projection (f16 mma, 256x128 tiles, 512 threads)
    mma_gemm<1><<<dim3(CC/128, NTOK/256), 512, gemm_smem>>>(ao, wprojT, b_proj,
                                                            out, NTOK, CC, CC);
}